// round 12
// baseline (speedup 1.0000x reference)
#include <cuda_runtime.h>
#include <cuda_bf16.h>
#include <math.h>
#include <stdint.h>

// Problem constants (fixed by setup_inputs)
#define BB 4
#define SS 8192
#define DD 512
#define HH 8
#define HD 64
#define BH 32      // B*H
#define UU 45      // int(5*ln(8193)) = 45 selected queries per (b,h)
#define NC 64      // candidate count for exact refinement
#define NSPLIT 16
#define CHUNK 512  // SS / NSPLIT

// ------------------------- device scratch -------------------------
static __device__ __align__(16) __nv_bfloat16 g_xb[(size_t)BB*SS*DD];  // 32 MB bf16 x
static __device__ __align__(16) __nv_bfloat16 g_wq[DD*DD];
static __device__ __align__(16) __nv_bfloat16 g_wk[DD*DD];
static __device__ __align__(16) __nv_bfloat16 g_wv[DD*DD];
static __device__ __align__(16) __nv_bfloat16 g_k[(size_t)BH*SS*HD];   // 32 MB [bh][s][d]
static __device__ __align__(16) __nv_bfloat16 g_v[(size_t)BH*SS*HD];   // 32 MB [bh][s][d]
static __device__ float g_sp[BH*SS];                               // approx ||q||^2
static __device__ int   g_cand[BH*NC];
static __device__ float g_csp[BH*NC];
static __device__ __align__(16) float g_cq[BH*NC*HD];
static __device__ int   g_top[BH*UU];
static __device__ __align__(16) float g_selq[BH*UU*HD];
static __device__ float g_selctx[BH*UU*HD];
static __device__ float g_vsum[BB*DD];                             // sum over S of v (no bias)
static __device__ __align__(16) float g_base[BB*DD];
static __device__ float g_pm[BH*NSPLIT*UU];
static __device__ float g_pl[BH*NSPLIT*UU];
static __device__ __align__(16) float g_pacc[(size_t)BH*NSPLIT*UU*HD];

// pack two floats to bf16x2 (lo -> bits[15:0], hi -> bits[31:16])
__device__ __forceinline__ uint32_t pk(float lo, float hi) {
    uint32_t r;
    asm("cvt.rn.bf16x2.f32 %0, %1, %2;" : "=r"(r) : "f"(hi), "f"(lo));
    return r;
}

__device__ __forceinline__ void ldsm4(uint32_t& r0, uint32_t& r1, uint32_t& r2,
                                      uint32_t& r3, uint32_t addr) {
    asm volatile("ldmatrix.sync.aligned.m8n8.x4.shared.b16 {%0,%1,%2,%3}, [%4];"
                 : "=r"(r0), "=r"(r1), "=r"(r2), "=r"(r3) : "r"(addr));
}
__device__ __forceinline__ void ldsm4t(uint32_t& r0, uint32_t& r1, uint32_t& r2,
                                       uint32_t& r3, uint32_t addr) {
    asm volatile("ldmatrix.sync.aligned.m8n8.x4.trans.shared.b16 {%0,%1,%2,%3}, [%4];"
                 : "=r"(r0), "=r"(r1), "=r"(r2), "=r"(r3) : "r"(addr));
}
__device__ __forceinline__ void mma16816(float* c, const uint32_t* a,
                                         uint32_t b0, uint32_t b1) {
    asm volatile(
        "mma.sync.aligned.m16n8k16.row.col.f32.bf16.bf16.f32 "
        "{%0,%1,%2,%3}, {%4,%5,%6,%7}, {%8,%9}, {%0,%1,%2,%3};\n"
        : "+f"(c[0]), "+f"(c[1]), "+f"(c[2]), "+f"(c[3])
        : "r"(a[0]), "r"(a[1]), "r"(a[2]), "r"(a[3]), "r"(b0), "r"(b1));
}

// ------------------------- fused converter + zero -------------------------
__global__ __launch_bounds__(256)
void cvt_all(const float* __restrict__ x,
             const float* __restrict__ Wq, const float* __restrict__ Wk,
             const float* __restrict__ Wv)
{
    const int blk = blockIdx.x;
    const int tid = threadIdx.x;
    if (blk < 16384) {
        int i = blk * 256 + tid;
        float4 v = ((const float4*)x)[i];
        uint2 o;
        o.x = pk(v.x, v.y);
        o.y = pk(v.z, v.w);
        ((uint2*)g_xb)[i] = o;
    } else if (blk < 17152) {
        int idx = blk - 16384;
        int w = idx >> 8;          // 0..2
        int i = (idx & 255) * 256 + tid;
        const float* src = (w == 0) ? Wq : (w == 1) ? Wk : Wv;
        __nv_bfloat16* dst = (w == 0) ? g_wq : (w == 1) ? g_wk : g_wv;
        float4 v = ((const float4*)src)[i];
        uint2 o;
        o.x = pk(v.x, v.y);
        o.y = pk(v.z, v.w);
        ((uint2*)dst)[i] = o;
    } else {
        int j = (blk - 17152) * 256 + tid;
        g_sp[j] = 0.f;
        if (j < BB * DD) g_vsum[j] = 0.f;
    }
}

// ------------------------- fused bf16 tensor-core projection GEMM -----------------
// Tile 128x256, BK=32, 8 warps (2M x 4N), warp tile 64x64, double-buffered smem.
// grid (256, 6): which = y>>1 (0=q,1=k,2=v), n0 = (y&1)*256.
// Each warp's 64 N-cols span exactly one head -> MODE0 sumsq is a plain store.
__global__ __launch_bounds__(256)
void proj_all(const float* __restrict__ bq, const float* __restrict__ bk,
              const float* __restrict__ bv)
{
    __shared__ __align__(16) uint32_t sAm[2][2048];   // A: 8 KB each buffer
    __shared__ __align__(16) uint32_t sBm[2][4096];   // B: 16 KB each buffer

    const int tid = threadIdx.x;
    const int lane = tid & 31, wid = tid >> 5;
    const int mwarp = wid >> 2, nwarp = wid & 3;
    const int which = blockIdx.y >> 1;
    const int m0 = blockIdx.x * 128, n0 = (blockIdx.y & 1) * 256;

    const __nv_bfloat16* __restrict__ X = g_xb;
    const __nv_bfloat16* __restrict__ W = (which == 0) ? g_wq : (which == 1) ? g_wk : g_wv;
    const float* __restrict__ bias = (which == 0) ? bq : (which == 1) ? bk : bv;

    // loaders: A thread = (row, 32B half); B thread = (row, 64B seg)
    const int rowA = tid >> 1, halfA = tid & 1;    // 128 rows x 2 halves (16 bf16)
    const int rowB = tid >> 3, segB = tid & 7;     // 32 rows x 8 segs (32 bf16)
    const __nv_bfloat16* gA = X + (size_t)(m0 + rowA) * DD + halfA * 16;
    const __nv_bfloat16* gB = W + (size_t)rowB * DD + n0 + segB * 32;

    // swizzled staging offsets (u32 index). A row = 16 u32; B row = 128 u32.
    const int usA = (rowA >> 1) & 3;
    const int aOff0 = rowA * 16 + ((halfA * 2)     ^ usA) * 4;
    const int aOff1 = rowA * 16 + ((halfA * 2 + 1) ^ usA) * 4;
    const int usB = rowB & 7;
    int bOff[4];
#pragma unroll
    for (int i = 0; i < 4; i++)
        bOff[i] = rowB * 128 + ((segB * 4 + i) ^ usB) * 4;

    uint4 a0, a1, bq4[4];
    a0 = *(const uint4*)(gA);
    a1 = *(const uint4*)(gA + 8);
#pragma unroll
    for (int i = 0; i < 4; i++) bq4[i] = *(const uint4*)(gB + i * 8);

    float acc[4][8][4];
#pragma unroll
    for (int mi = 0; mi < 4; mi++)
#pragma unroll
        for (int ni = 0; ni < 8; ni++)
#pragma unroll
            for (int c = 0; c < 4; c++) acc[mi][ni][c] = 0.f;

    const uint32_t aBase = (uint32_t)__cvta_generic_to_shared(&sAm[0][0]);
    const uint32_t bBase = (uint32_t)__cvta_generic_to_shared(&sBm[0][0]);

    const int ro  = lane & 15;
    const int ch2 = (lane >> 4) & 1;
    const int rs2 = (ro >> 1) & 3;
    const int rs7 = ro & 7;

    auto stage = [&](int buf) {
        *(uint4*)&sAm[buf][aOff0] = a0;
        *(uint4*)&sAm[buf][aOff1] = a1;
#pragma unroll
        for (int i = 0; i < 4; i++) *(uint4*)&sBm[buf][bOff[i]] = bq4[i];
    };

    stage(0);
    __syncthreads();

    for (int chn = 0; chn < 16; chn++) {
        if (chn < 15) {
            const __nv_bfloat16* pA = gA + (chn + 1) * 32;
            const __nv_bfloat16* pB = gB + (size_t)(chn + 1) * 32 * DD;
            a0 = *(const uint4*)(pA);
            a1 = *(const uint4*)(pA + 8);
#pragma unroll
            for (int i = 0; i < 4; i++) bq4[i] = *(const uint4*)(pB + i * 8);
        }
        {
            const uint32_t ab = aBase + (chn & 1) * 8192;
            const uint32_t bb = bBase + (chn & 1) * 16384;
#pragma unroll
            for (int kblk = 0; kblk < 2; kblk++) {
                uint32_t af[4][4];
#pragma unroll
                for (int mi = 0; mi < 4; mi++) {
                    int row = mwarp * 64 + mi * 16 + ro;
                    int u = (kblk * 2 + ch2) ^ rs2;
                    ldsm4(af[mi][0], af[mi][1], af[mi][2], af[mi][3],
                          ab + (row * 16 + u * 4) * 4);
                }
                uint32_t bf[4][4];
#pragma unroll
                for (int np = 0; np < 4; np++) {
                    int row = kblk * 16 + ro;
                    int u = (nwarp * 8 + np * 2 + ch2) ^ rs7;
                    ldsm4t(bf[np][0], bf[np][1], bf[np][2], bf[np][3],
                           bb + (row * 128 + u * 4) * 4);
                }
#pragma unroll
                for (int mi = 0; mi < 4; mi++)
#pragma unroll
                    for (int ni = 0; ni < 8; ni++)
                        mma16816(acc[mi][ni], af[mi],
                                 bf[ni >> 1][(ni & 1) * 2], bf[ni >> 1][(ni & 1) * 2 + 1]);
            }
        }
        if (chn < 15) stage((chn + 1) & 1);
        __syncthreads();
    }

    // ---------------- epilogue ----------------
    const int g = lane >> 2, tig = lane & 3;

    float bn[8][2];
#pragma unroll
    for (int ni = 0; ni < 8; ni++) {
        int n = n0 + nwarp * 64 + ni * 8 + tig * 2;
        bn[ni][0] = bias[n];
        bn[ni][1] = bias[n + 1];
    }

    if (which == 0) {
        const int h = (n0 + nwarp * 64) >> 6;   // warp's 64 cols = exactly one head
#pragma unroll
        for (int mi = 0; mi < 4; mi++) {
            int m = m0 + mwarp * 64 + mi * 16 + g;
            int b = m >> 13;
            int s = m & (SS - 1);
            float ss0 = 0.f, ss1 = 0.f;
#pragma unroll
            for (int ni = 0; ni < 8; ni++) {
                float c0 = acc[mi][ni][0] + bn[ni][0];
                float c1 = acc[mi][ni][1] + bn[ni][1];
                float c2 = acc[mi][ni][2] + bn[ni][0];
                float c3 = acc[mi][ni][3] + bn[ni][1];
                ss0 = fmaf(c0, c0, fmaf(c1, c1, ss0));
                ss1 = fmaf(c2, c2, fmaf(c3, c3, ss1));
            }
            ss0 += __shfl_xor_sync(0xffffffffu, ss0, 1);
            ss0 += __shfl_xor_sync(0xffffffffu, ss0, 2);
            ss1 += __shfl_xor_sync(0xffffffffu, ss1, 1);
            ss1 += __shfl_xor_sync(0xffffffffu, ss1, 2);
            if (tig == 0) {
                g_sp[(b * HH + h) * SS + s]     = ss0;   // full head -> plain store
                g_sp[(b * HH + h) * SS + s + 8] = ss1;
            }
        }
    } else {
        __nv_bfloat16* __restrict__ dst = (which == 1) ? g_k : g_v;
        const int h = (n0 + nwarp * 64) >> 6;
#pragma unroll
        for (int mi = 0; mi < 4; mi++) {
            int m = m0 + mwarp * 64 + mi * 16 + g;
            int b = m >> 13;
            int s = m & (SS - 1);
#pragma unroll
            for (int ni = 0; ni < 8; ni++) {
                int d = (nwarp * 64 + ni * 8 + tig * 2) & 63;
                uint32_t lo = pk(acc[mi][ni][0] + bn[ni][0], acc[mi][ni][1] + bn[ni][1]);
                uint32_t hi = pk(acc[mi][ni][2] + bn[ni][0], acc[mi][ni][3] + bn[ni][1]);
                *(uint32_t*)(dst + (((size_t)(b * HH + h)) * SS + s) * HD + d)     = lo;
                *(uint32_t*)(dst + (((size_t)(b * HH + h)) * SS + s + 8) * HD + d) = hi;
            }
        }
        if (which == 2) {
            const int b = m0 >> 13;
#pragma unroll
            for (int ni = 0; ni < 8; ni++) {
                float s0 = 0.f, s1 = 0.f;
#pragma unroll
                for (int mi = 0; mi < 4; mi++) {
                    s0 += acc[mi][ni][0] + acc[mi][ni][2];
                    s1 += acc[mi][ni][1] + acc[mi][ni][3];
                }
#pragma unroll
                for (int off = 4; off <= 16; off <<= 1) {
                    s0 += __shfl_xor_sync(0xffffffffu, s0, off);
                    s1 += __shfl_xor_sync(0xffffffffu, s1, off);
                }
                if (g == 0) {
                    int n = n0 + nwarp * 64 + ni * 8 + tig * 2;
                    atomicAdd(&g_vsum[b * DD + n], s0);
                    atomicAdd(&g_vsum[b * DD + n + 1], s1);
                }
            }
        }
    }
}

// ------------------------- histogram top-64 selection -------------------------
__global__ __launch_bounds__(256) void topk_radix()
{
    __shared__ uint32_t hist[4096];     // 16 KB
    __shared__ float    cv[2048];       // 8 KB
    __shared__ int      ci[2048];       // 8 KB
    __shared__ uint32_t gsum[256];
    __shared__ uint32_t s_thr, s_cnt;
    const int bh = blockIdx.x;
    const int tid = threadIdx.x;
#pragma unroll
    for (int i = 0; i < 16; i++) hist[tid + i * 256] = 0;
    if (tid == 0) s_cnt = 0;
    __syncthreads();

    const float* sp = g_sp + bh * SS;
    uint32_t ub[32];
#pragma unroll
    for (int i = 0; i < 32; i++) {
        ub[i] = __float_as_uint(sp[tid + i * 256]);
        atomicAdd(&hist[ub[i] >> 20], 1u);
    }
    __syncthreads();

    uint32_t gs = 0;
#pragma unroll
    for (int i = 0; i < 16; i++) gs += hist[tid * 16 + i];
    gsum[tid] = gs;
    __syncthreads();

    if (tid == 0) {
        uint32_t cum = 0;
        int g = 255;
        for (; g > 0; g--) {
            if (cum + gsum[g] >= NC) break;
            cum += gsum[g];
        }
        int b = g * 16 + 15;
        for (; b > g * 16; b--) {
            cum += hist[b];
            if (cum >= NC) break;
        }
        s_thr = (uint32_t)b;
    }
    __syncthreads();
    const uint32_t thr = s_thr;

#pragma unroll
    for (int i = 0; i < 32; i++) {
        if ((ub[i] >> 20) >= thr) {
            uint32_t p = atomicAdd(&s_cnt, 1u);
            if (p < 2048) { cv[p] = __uint_as_float(ub[i]); ci[p] = tid + i * 256; }
        }
    }
    __syncthreads();
    int C = (int)s_cnt;
    if (C > 2048) C = 2048;
    for (int c = tid; c < C; c += 256) {
        float myv = cv[c];
        int   myi = ci[c];
        int rank = 0;
        for (int j = 0; j < C; j++) {
            float o = cv[j];
            rank += (o > myv) || (o == myv && ci[j] < myi);
        }
        if (rank < NC) g_cand[bh * NC + rank] = myi;
    }
}

// ------------------------- exact fp32 recompute of candidate q rows ---------------
__global__ __launch_bounds__(256)
void cand_refine(const float* __restrict__ X, const float* __restrict__ Wq,
                 const float* __restrict__ bq)
{
    __shared__ float sW[64][65];
    __shared__ float sX[8][64];
    __shared__ int   sS_[8];
    const int bh = blockIdx.x, grp = blockIdx.y;
    const int b = bh >> 3, h = bh & 7;
    const int tid = threadIdx.x;
    const int u = tid >> 5, lane = tid & 31;
    if (tid < 8) sS_[tid] = g_cand[bh * NC + grp * 8 + tid];
    float acc0 = 0.f, acc1 = 0.f;
    __syncthreads();
    for (int kc = 0; kc < 8; kc++) {
#pragma unroll
        for (int i = 0; i < 16; i++) {
            int idx = tid + i * 256;
            sW[idx >> 6][idx & 63] = Wq[(size_t)(kc * 64 + (idx >> 6)) * DD + h * HD + (idx & 63)];
        }
#pragma unroll
        for (int i = 0; i < 2; i++) {
            int idx = tid + i * 256;
            sX[idx >> 6][idx & 63] = X[((size_t)b * SS + sS_[idx >> 6]) * DD + kc * 64 + (idx & 63)];
        }
        __syncthreads();
#pragma unroll
        for (int k = 0; k < 64; k++) {
            float xv = sX[u][k];
            acc0 = fmaf(xv, sW[k][lane], acc0);
            acc1 = fmaf(xv, sW[k][lane + 32], acc1);
        }
        __syncthreads();
    }
    acc0 += bq[h * HD + lane];
    acc1 += bq[h * HD + lane + 32];
    const int cu = bh * NC + grp * 8 + u;
    g_cq[cu * HD + lane] = acc0;
    g_cq[cu * HD + lane + 32] = acc1;
    float ss = acc0 * acc0 + acc1 * acc1;
#pragma unroll
    for (int off = 16; off > 0; off >>= 1) ss += __shfl_xor_sync(0xffffffffu, ss, off);
    if (lane == 0) g_csp[cu] = ss;
}

// ------------------------- exact top-45 among candidates -------------------------
__global__ __launch_bounds__(64) void final_sel()
{
    __shared__ float vv[NC];
    __shared__ int   ssd[NC];
    __shared__ int   slot[UU];
    const int bh = blockIdx.x;
    const int tid = threadIdx.x;
    float myv = g_csp[bh * NC + tid];
    int   mys = g_cand[bh * NC + tid];
    vv[tid] = myv; ssd[tid] = mys;
    __syncthreads();
    int rank = 0;
#pragma unroll
    for (int j = 0; j < NC; j++) {
        float o = vv[j];
        if (o > myv || (o == myv && ssd[j] < mys)) rank++;
    }
    if (rank < UU) { g_top[bh * UU + rank] = mys; slot[rank] = tid; }
    __syncthreads();
    for (int u = 0; u < UU; u++) {
        int c = slot[u];
        g_selq[(bh * UU + u) * HD + tid] = g_cq[(bh * NC + c) * HD + tid];
    }
}

// ------------------------- tensor-core flash attention (split-K over S) -----------
__global__ __launch_bounds__(256)
void attn_mma()
{
    __shared__ __align__(16) uint8_t sQ[48 * 128];    // bf16 swizzled
    __shared__ __align__(16) uint8_t sKV[64 * 128];   // K then V (bf16 swizzled)
    __shared__ __align__(16) uint8_t sPb[48 * 128];   // P bf16 swizzled
    __shared__ float sS[48][66];                      // raw scores fp32
    __shared__ float sm[48], sl[48], salpha[48];

    const int bh = blockIdx.x, sp = blockIdx.y;
    const int tid = threadIdx.x;
    const int lane = tid & 31, w = tid >> 5;
    const uint32_t qb = (uint32_t)__cvta_generic_to_shared(sQ);
    const uint32_t kb = (uint32_t)__cvta_generic_to_shared(sKV);
    const uint32_t pbm = (uint32_t)__cvta_generic_to_shared(sPb);

    for (int c = tid; c < 384; c += 256) {
        int r = c >> 3, u = c & 7;
        uint4 val = make_uint4(0, 0, 0, 0);
        if (r < UU) {
            const float* src = g_selq + ((size_t)bh * UU + r) * HD + u * 8;
            float4 f0 = *(const float4*)src;
            float4 f1 = *(const float4*)(src + 4);
            val.x = pk(f0.x * 0.125f, f0.y * 0.125f);
            val.y = pk(f0.z * 0.125f, f0.w * 0.125f);
            val.z = pk(f1.x * 0.125f, f1.y * 0.125f);
            val.w = pk(f1.z * 0.125f, f1.w * 0.125f);
        }
        *(uint4*)(sQ + r * 128 + ((u ^ (r & 7)) * 16)) = val;
    }
    if (tid < 48) { sm[tid] = -INFINITY; sl[tid] = 0.f; }

    float acc[3][4];
#pragma unroll
    for (int mt = 0; mt < 3; mt++)
#pragma unroll
        for (int c = 0; c < 4; c++) acc[mt][c] = 0.f;

    const __nv_bfloat16* kvK = g_k + ((size_t)bh * SS + sp * CHUNK) * HD;
    const __nv_bfloat16* kvV = g_v + ((size_t)bh * SS + sp * CHUNK) * HD;

    const int ro = lane & 15, ch2 = (lane >> 4) & 1;
    const int g = lane >> 2, tg = lane & 3;

    for (int t = 0; t < 8; t++) {
        __syncthreads();
        for (int c = tid; c < 512; c += 256) {
            int r = c >> 3, u = c & 7;
            uint4 val = *(const uint4*)(kvK + ((size_t)(t * 64 + r)) * HD + u * 8);
            *(uint4*)(sKV + r * 128 + ((u ^ (r & 7)) * 16)) = val;
        }
        __syncthreads();

        float Cr[3][4];
#pragma unroll
        for (int mt = 0; mt < 3; mt++)
#pragma unroll
            for (int c = 0; c < 4; c++) Cr[mt][c] = 0.f;
#pragma unroll
        for (int ks = 0; ks < 4; ks++) {
            uint32_t br[4];
            {
                int row = (w >> 1) * 16 + ro;
                ldsm4(br[0], br[1], br[2], br[3],
                      kb + row * 128 + (((ks * 2 + ch2) ^ (row & 7)) * 16));
            }
            uint32_t b0 = br[w & 1], b1 = br[(w & 1) + 2];
#pragma unroll
            for (int mt = 0; mt < 3; mt++) {
                uint32_t a[4];
                int row = mt * 16 + ro;
                ldsm4(a[0], a[1], a[2], a[3],
                      qb + row * 128 + (((ks * 2 + ch2) ^ (row & 7)) * 16));
                mma16816(Cr[mt], a, b0, b1);
            }
        }
#pragma unroll
        for (int mt = 0; mt < 3; mt++) {
            int col = w * 8 + tg * 2;
            sS[mt * 16 + g][col]     = Cr[mt][0];
            sS[mt * 16 + g][col + 1] = Cr[mt][1];
            sS[mt * 16 + g + 8][col]     = Cr[mt][2];
            sS[mt * 16 + g + 8][col + 1] = Cr[mt][3];
        }
        __syncthreads();

        for (int c = tid; c < 512; c += 256) {
            int r = c >> 3, u = c & 7;
            uint4 val = *(const uint4*)(kvV + ((size_t)(t * 64 + r)) * HD + u * 8);
            *(uint4*)(sKV + r * 128 + ((u ^ (r & 7)) * 16)) = val;
        }
        if (tid < 192) {
            int r = tid >> 2, qt = tid & 3;
            float mx = -INFINITY;
#pragma unroll
            for (int j = 0; j < 16; j++) mx = fmaxf(mx, sS[r][qt * 16 + j]);
            mx = fmaxf(mx, __shfl_xor_sync(0xffffffffu, mx, 1));
            mx = fmaxf(mx, __shfl_xor_sync(0xffffffffu, mx, 2));
            if (qt == 0) {
                float mnew = fmaxf(sm[r], mx);
                salpha[r] = __expf(sm[r] - mnew);
                sm[r] = mnew;
            }
        }
        __syncthreads();

#pragma unroll
        for (int mt = 0; mt < 3; mt++) {
            float a0 = salpha[mt * 16 + g];
            float a1 = salpha[mt * 16 + g + 8];
            acc[mt][0] *= a0; acc[mt][1] *= a0;
            acc[mt][2] *= a1; acc[mt][3] *= a1;
        }
        if (tid < 192) {
            int r = tid >> 2, qt = tid & 3;
            float mr = sm[r];
            float e[16], ls = 0.f;
#pragma unroll
            for (int j = 0; j < 16; j++) {
                e[j] = __expf(sS[r][qt * 16 + j] - mr);
                ls += e[j];
            }
            uint4 v0, v1;
            v0.x = pk(e[0], e[1]);   v0.y = pk(e[2], e[3]);
            v0.z = pk(e[4], e[5]);   v0.w = pk(e[6], e[7]);
            v1.x = pk(e[8], e[9]);   v1.y = pk(e[10], e[11]);
            v1.z = pk(e[12], e[13]); v1.w = pk(e[14], e[15]);
            *(uint4*)(sPb + r * 128 + (((qt * 2)     ^ (r & 7)) * 16)) = v0;
            *(uint4*)(sPb + r * 128 + (((qt * 2 + 1) ^ (r & 7)) * 16)) = v1;
            ls += __shfl_xor_sync(0xffffffffu, ls, 1);
            ls += __shfl_xor_sync(0xffffffffu, ls, 2);
            if (qt == 0) sl[r] = sl[r] * salpha[r] + ls;
        }
        __syncthreads();

#pragma unroll
        for (int ks = 0; ks < 4; ks++) {
            uint32_t br[4];
            {
                int row = ks * 16 + ro;
                ldsm4t(br[0], br[1], br[2], br[3],
                       kb + row * 128 + ((((w >> 1) * 2 + ch2) ^ (row & 7)) * 16));
            }
            uint32_t b0 = br[(w & 1) * 2], b1 = br[(w & 1) * 2 + 1];
#pragma unroll
            for (int mt = 0; mt < 3; mt++) {
                uint32_t a[4];
                int row = mt * 16 + ro;
                ldsm4(a[0], a[1], a[2], a[3],
                      pbm + row * 128 + (((ks * 2 + ch2) ^ (row & 7)) * 16));
                mma16816(acc[mt], a, b0, b1);
            }
        }
    }

    const int pbase = (bh * NSPLIT + sp) * UU;
    if (tid < UU) { g_pm[pbase + tid] = sm[tid]; g_pl[pbase + tid] = sl[tid]; }
#pragma unroll
    for (int mt = 0; mt < 3; mt++) {
        int q0 = mt * 16 + g, q1 = q0 + 8;
        int d = w * 8 + tg * 2;
        if (q0 < UU)
            *(float2*)(g_pacc + ((size_t)(pbase + q0)) * HD + d) = make_float2(acc[mt][0], acc[mt][1]);
        if (q1 < UU)
            *(float2*)(g_pacc + ((size_t)(pbase + q1)) * HD + d) = make_float2(acc[mt][2], acc[mt][3]);
    }
}

// ------------------------- split-K merge -------------------------
__global__ __launch_bounds__(64) void merge_kernel()
{
    const int bh = blockIdx.x, u = blockIdx.y;
    const int d = threadIdx.x;
    float M = -INFINITY;
#pragma unroll
    for (int i = 0; i < NSPLIT; i++)
        M = fmaxf(M, g_pm[(bh * NSPLIT + i) * UU + u]);
    float L = 0.f, ctx = 0.f;
    for (int i = 0; i < NSPLIT; i++) {
        int pi = (bh * NSPLIT + i) * UU + u;
        float w = __expf(g_pm[pi] - M);
        L += g_pl[pi] * w;
        ctx += g_pacc[(size_t)pi * HD + d] * w;
    }
    g_selctx[(bh * UU + u) * HD + d] = ctx / L;
}

// ------------------------- output base, broadcast, corrections -------------------------
__global__ __launch_bounds__(512)
void base_kernel(const float* __restrict__ Wo, const float* __restrict__ bo,
                 const float* __restrict__ bv)
{
    __shared__ float vm[DD];
    const int b = blockIdx.x;
    const int n = threadIdx.x;
    vm[n] = g_vsum[b * DD + n] * (1.f / SS) + bv[n];
    __syncthreads();
    float a = bo[n];
    for (int kk = 0; kk < DD; kk++)
        a = fmaf(vm[kk], Wo[(size_t)kk * DD + n], a);
    g_base[b * DD + n] = a;
}

__global__ __launch_bounds__(256) void bcast_kernel(float* __restrict__ out)
{
    __shared__ float4 bs[128];
    const int row0 = blockIdx.x * 16;
    const int b = row0 >> 13;
    if (threadIdx.x < 128)
        bs[threadIdx.x] = ((const float4*)(g_base + b * DD))[threadIdx.x];
    __syncthreads();
    float4* o = (float4*)out + (size_t)row0 * 128;
    for (int i = threadIdx.x; i < 16 * 128; i += 256)
        o[i] = bs[i & 127];
}

__global__ __launch_bounds__(512)
void corr_kernel(const float* __restrict__ Wo, const float* __restrict__ bv,
                 float* __restrict__ out)
{
    __shared__ float delta[64];
    __shared__ int ssel;
    const int bh = blockIdx.x, u = blockIdx.y;
    const int b = bh >> 3, h = bh & 7;
    const int tid = threadIdx.x;
    if (tid == 0) ssel = g_top[bh * UU + u];
    if (tid < 64)
        delta[tid] = g_selctx[(bh * UU + u) * HD + tid]
                   - (g_vsum[bh * HD + tid] * (1.f / SS) + bv[h * HD + tid]);
    __syncthreads();
    const int s = ssel;
    float a = 0.f;
#pragma unroll
    for (int d = 0; d < 64; d++)
        a = fmaf(delta[d], Wo[(size_t)(h * HD + d) * DD + tid], a);
    atomicAdd(out + ((size_t)b * SS + s) * DD + tid, a);
}

// ------------------------- launch -------------------------
extern "C" void kernel_launch(void* const* d_in, const int* in_sizes, int n_in,
                              void* d_out, int out_size)
{
    (void)in_sizes; (void)n_in; (void)out_size;
    const float* x  = (const float*)d_in[0];
    const float* Wq = (const float*)d_in[1];
    const float* bq = (const float*)d_in[2];
    const float* Wk = (const float*)d_in[3];
    const float* bk = (const float*)d_in[4];
    const float* Wv = (const float*)d_in[5];
    const float* bv = (const float*)d_in[6];
    const float* Wo = (const float*)d_in[7];
    const float* bo = (const float*)d_in[8];
    float* out = (float*)d_out;

    cvt_all<<<18176, 256>>>(x, Wq, Wk, Wv);
    proj_all<<<dim3(256, 6), 256>>>(bq, bk, bv);
    topk_radix<<<BH, 256>>>();
    cand_refine<<<dim3(BH, NC / 8), 256>>>(x, Wq, bq);
    final_sel<<<BH, 64>>>();
    attn_mma<<<dim3(BH, NSPLIT), 256>>>();
    merge_kernel<<<dim3(BH, UU), HD>>>();
    base_kernel<<<BB, DD>>>(Wo, bo, bv);
    bcast_kernel<<<BB * SS / 16, 256>>>(out);
    corr_kernel<<<dim3(BH, UU), DD>>>(Wo, bv, out);
}

// round 13
// speedup vs baseline: 1.0795x; 1.0795x over previous
#include <cuda_runtime.h>
#include <cuda_bf16.h>
#include <math.h>
#include <stdint.h>

// Problem constants (fixed by setup_inputs)
#define BB 4
#define SS 8192
#define DD 512
#define HH 8
#define HD 64
#define BH 32      // B*H
#define UU 45      // int(5*ln(8193)) = 45 selected queries per (b,h)
#define NC 64      // candidate count for exact refinement
#define NSPLIT 16
#define CHUNK 512  // SS / NSPLIT

// ------------------------- device scratch -------------------------
static __device__ __align__(16) __nv_bfloat16 g_xb[(size_t)BB*SS*DD];  // 32 MB bf16 x
static __device__ __align__(16) __nv_bfloat16 g_wq[DD*DD];
static __device__ __align__(16) __nv_bfloat16 g_wk[DD*DD];
static __device__ __align__(16) __nv_bfloat16 g_wv[DD*DD];
static __device__ __align__(16) __nv_bfloat16 g_k[(size_t)BH*SS*HD];   // 32 MB [bh][s][d]
static __device__ __align__(16) __nv_bfloat16 g_v[(size_t)BH*SS*HD];   // 32 MB [bh][s][d]
static __device__ float g_sp[BH*SS];                               // approx ||q||^2
static __device__ int   g_cand[BH*NC];
static __device__ float g_csp[BH*NC];
static __device__ __align__(16) float g_cq[BH*NC*HD];
static __device__ int   g_top[BH*UU];
static __device__ __align__(16) float g_selq[BH*UU*HD];
static __device__ float g_vsum[BB*DD];                             // sum over S of v (no bias)
static __device__ __align__(16) float g_base[BB*DD];
static __device__ float g_pm[BH*NSPLIT*UU];
static __device__ float g_pl[BH*NSPLIT*UU];
static __device__ __align__(16) float g_pacc[(size_t)BH*NSPLIT*UU*HD];

// pack two floats to bf16x2 (lo -> bits[15:0], hi -> bits[31:16])
__device__ __forceinline__ uint32_t pk(float lo, float hi) {
    uint32_t r;
    asm("cvt.rn.bf16x2.f32 %0, %1, %2;" : "=r"(r) : "f"(hi), "f"(lo));
    return r;
}

__device__ __forceinline__ void ldsm4(uint32_t& r0, uint32_t& r1, uint32_t& r2,
                                      uint32_t& r3, uint32_t addr) {
    asm volatile("ldmatrix.sync.aligned.m8n8.x4.shared.b16 {%0,%1,%2,%3}, [%4];"
                 : "=r"(r0), "=r"(r1), "=r"(r2), "=r"(r3) : "r"(addr));
}
__device__ __forceinline__ void ldsm4t(uint32_t& r0, uint32_t& r1, uint32_t& r2,
                                       uint32_t& r3, uint32_t addr) {
    asm volatile("ldmatrix.sync.aligned.m8n8.x4.trans.shared.b16 {%0,%1,%2,%3}, [%4];"
                 : "=r"(r0), "=r"(r1), "=r"(r2), "=r"(r3) : "r"(addr));
}
__device__ __forceinline__ void mma16816(float* c, const uint32_t* a,
                                         uint32_t b0, uint32_t b1) {
    asm volatile(
        "mma.sync.aligned.m16n8k16.row.col.f32.bf16.bf16.f32 "
        "{%0,%1,%2,%3}, {%4,%5,%6,%7}, {%8,%9}, {%0,%1,%2,%3};\n"
        : "+f"(c[0]), "+f"(c[1]), "+f"(c[2]), "+f"(c[3])
        : "r"(a[0]), "r"(a[1]), "r"(a[2]), "r"(a[3]), "r"(b0), "r"(b1));
}

// ------------------------- fused converter + zero -------------------------
__global__ __launch_bounds__(256)
void cvt_all(const float* __restrict__ x,
             const float* __restrict__ Wq, const float* __restrict__ Wk,
             const float* __restrict__ Wv)
{
    const int blk = blockIdx.x;
    const int tid = threadIdx.x;
    if (blk < 16384) {
        int i = blk * 256 + tid;
        float4 v = ((const float4*)x)[i];
        uint2 o;
        o.x = pk(v.x, v.y);
        o.y = pk(v.z, v.w);
        ((uint2*)g_xb)[i] = o;
    } else if (blk < 17152) {
        int idx = blk - 16384;
        int w = idx >> 8;          // 0..2
        int i = (idx & 255) * 256 + tid;
        const float* src = (w == 0) ? Wq : (w == 1) ? Wk : Wv;
        __nv_bfloat16* dst = (w == 0) ? g_wq : (w == 1) ? g_wk : g_wv;
        float4 v = ((const float4*)src)[i];
        uint2 o;
        o.x = pk(v.x, v.y);
        o.y = pk(v.z, v.w);
        ((uint2*)dst)[i] = o;
    } else {
        int j = (blk - 17152) * 256 + tid;
        g_sp[j] = 0.f;
        if (j < BB * DD) g_vsum[j] = 0.f;
    }
}

// ------------------------- fused bf16 tensor-core projection GEMM -----------------
// Round-11 anchor: tile 128x128, BK=32, 8 warps (2M x 4N), warp tile 64x32,
// double-buffered register-staged smem, 2 CTAs/SM.
// grid (256, 12): which = y>>2 (0=q,1=k,2=v), n0=(y&3)*128.
__global__ __launch_bounds__(256)
void proj_all(const float* __restrict__ bq, const float* __restrict__ bk,
              const float* __restrict__ bv)
{
    __shared__ __align__(16) uint32_t sAm[2][2048];   // 8 KB each
    __shared__ __align__(16) uint32_t sBm[2][2048];   // 8 KB each

    const int tid = threadIdx.x;
    const int lane = tid & 31, wid = tid >> 5;
    const int mwarp = wid >> 2, nwarp = wid & 3;
    const int which = blockIdx.y >> 2;
    const int m0 = blockIdx.x * 128, n0 = (blockIdx.y & 3) * 128;

    const __nv_bfloat16* __restrict__ X = g_xb;
    const __nv_bfloat16* __restrict__ W = (which == 0) ? g_wq : (which == 1) ? g_wk : g_wv;
    const float* __restrict__ bias = (which == 0) ? bq : (which == 1) ? bk : bv;

    const int rowA = tid >> 1, halfA = tid & 1;
    const int rowB = tid >> 3, segB = tid & 7;
    const __nv_bfloat16* gA = X + (size_t)(m0 + rowA) * DD + halfA * 16;
    const __nv_bfloat16* gB = W + (size_t)rowB * DD + n0 + segB * 16;

    const int usA = (rowA >> 1) & 3;
    const int aOff0 = rowA * 16 + ((halfA * 2)     ^ usA) * 4;
    const int aOff1 = rowA * 16 + ((halfA * 2 + 1) ^ usA) * 4;
    const int usB = rowB & 7;
    const int bOff0 = rowB * 64 + ((segB * 2)     ^ usB) * 4;
    const int bOff1 = rowB * 64 + ((segB * 2 + 1) ^ usB) * 4;

    uint4 a0, a1, b0, b1;
    a0 = *(const uint4*)(gA);
    a1 = *(const uint4*)(gA + 8);
    b0 = *(const uint4*)(gB);
    b1 = *(const uint4*)(gB + 8);

    float acc[4][4][4];
#pragma unroll
    for (int mi = 0; mi < 4; mi++)
#pragma unroll
        for (int ni = 0; ni < 4; ni++)
#pragma unroll
            for (int c = 0; c < 4; c++) acc[mi][ni][c] = 0.f;

    const uint32_t aBase = (uint32_t)__cvta_generic_to_shared(&sAm[0][0]);
    const uint32_t bBase = (uint32_t)__cvta_generic_to_shared(&sBm[0][0]);

    const int ro  = lane & 15;
    const int ch2 = (lane >> 4) & 1;
    const int rs2 = (ro >> 1) & 3;
    const int rs7 = ro & 7;

    auto stage = [&](int buf) {
        *(uint4*)&sAm[buf][aOff0] = a0;
        *(uint4*)&sAm[buf][aOff1] = a1;
        *(uint4*)&sBm[buf][bOff0] = b0;
        *(uint4*)&sBm[buf][bOff1] = b1;
    };

    stage(0);
    __syncthreads();

    for (int chn = 0; chn < 16; chn++) {
        if (chn < 15) {
            const __nv_bfloat16* pA = gA + (chn + 1) * 32;
            const __nv_bfloat16* pB = gB + (size_t)(chn + 1) * 32 * DD;
            a0 = *(const uint4*)(pA);
            a1 = *(const uint4*)(pA + 8);
            b0 = *(const uint4*)(pB);
            b1 = *(const uint4*)(pB + 8);
        }
        {
            const uint32_t ab = aBase + (chn & 1) * 8192;
            const uint32_t bb = bBase + (chn & 1) * 8192;
#pragma unroll
            for (int kblk = 0; kblk < 2; kblk++) {
                uint32_t af[4][4];
#pragma unroll
                for (int mi = 0; mi < 4; mi++) {
                    int row = mwarp * 64 + mi * 16 + ro;
                    int u = (kblk * 2 + ch2) ^ rs2;
                    ldsm4(af[mi][0], af[mi][1], af[mi][2], af[mi][3],
                          ab + (row * 16 + u * 4) * 4);
                }
                uint32_t bf[2][4];
#pragma unroll
                for (int np = 0; np < 2; np++) {
                    int row = kblk * 16 + ro;
                    int u = (nwarp * 4 + np * 2 + ch2) ^ rs7;
                    ldsm4t(bf[np][0], bf[np][1], bf[np][2], bf[np][3],
                           bb + (row * 64 + u * 4) * 4);
                }
#pragma unroll
                for (int mi = 0; mi < 4; mi++)
#pragma unroll
                    for (int ni = 0; ni < 4; ni++)
                        mma16816(acc[mi][ni], af[mi],
                                 bf[ni >> 1][(ni & 1) * 2], bf[ni >> 1][(ni & 1) * 2 + 1]);
            }
        }
        if (chn < 15) stage((chn + 1) & 1);
        __syncthreads();
    }

    const int g = lane >> 2, tig = lane & 3;

    float bn[4][2];
#pragma unroll
    for (int ni = 0; ni < 4; ni++) {
        int n = n0 + nwarp * 32 + ni * 8 + tig * 2;
        bn[ni][0] = bias[n];
        bn[ni][1] = bias[n + 1];
    }

    if (which == 0) {
        const int h = (n0 + nwarp * 32) >> 6;
#pragma unroll
        for (int mi = 0; mi < 4; mi++) {
            int m = m0 + mwarp * 64 + mi * 16 + g;
            int b = m >> 13;
            int s = m & (SS - 1);
            float ss0 = 0.f, ss1 = 0.f;
#pragma unroll
            for (int ni = 0; ni < 4; ni++) {
                float c0 = acc[mi][ni][0] + bn[ni][0];
                float c1 = acc[mi][ni][1] + bn[ni][1];
                float c2 = acc[mi][ni][2] + bn[ni][0];
                float c3 = acc[mi][ni][3] + bn[ni][1];
                ss0 = fmaf(c0, c0, fmaf(c1, c1, ss0));
                ss1 = fmaf(c2, c2, fmaf(c3, c3, ss1));
            }
            ss0 += __shfl_xor_sync(0xffffffffu, ss0, 1);
            ss0 += __shfl_xor_sync(0xffffffffu, ss0, 2);
            ss1 += __shfl_xor_sync(0xffffffffu, ss1, 1);
            ss1 += __shfl_xor_sync(0xffffffffu, ss1, 2);
            if (tig == 0) {
                atomicAdd(&g_sp[(b * HH + h) * SS + s], ss0);
                atomicAdd(&g_sp[(b * HH + h) * SS + s + 8], ss1);
            }
        }
    } else {
        __nv_bfloat16* __restrict__ dst = (which == 1) ? g_k : g_v;
#pragma unroll
        for (int mi = 0; mi < 4; mi++) {
            int m = m0 + mwarp * 64 + mi * 16 + g;
            int b = m >> 13;
            int s = m & (SS - 1);
#pragma unroll
            for (int ni = 0; ni < 4; ni++) {
                int n = n0 + nwarp * 32 + ni * 8 + tig * 2;
                int h = n >> 6, d = n & 63;
                uint32_t lo = pk(acc[mi][ni][0] + bn[ni][0], acc[mi][ni][1] + bn[ni][1]);
                uint32_t hi = pk(acc[mi][ni][2] + bn[ni][0], acc[mi][ni][3] + bn[ni][1]);
                *(uint32_t*)(dst + (((size_t)(b * HH + h)) * SS + s) * HD + d)     = lo;
                *(uint32_t*)(dst + (((size_t)(b * HH + h)) * SS + s + 8) * HD + d) = hi;
            }
        }
        if (which == 2) {
            const int b = m0 >> 13;
#pragma unroll
            for (int ni = 0; ni < 4; ni++) {
                float s0 = 0.f, s1 = 0.f;
#pragma unroll
                for (int mi = 0; mi < 4; mi++) {
                    s0 += acc[mi][ni][0] + acc[mi][ni][2];
                    s1 += acc[mi][ni][1] + acc[mi][ni][3];
                }
#pragma unroll
                for (int off = 4; off <= 16; off <<= 1) {
                    s0 += __shfl_xor_sync(0xffffffffu, s0, off);
                    s1 += __shfl_xor_sync(0xffffffffu, s1, off);
                }
                if (g == 0) {
                    int n = n0 + nwarp * 32 + ni * 8 + tig * 2;
                    atomicAdd(&g_vsum[b * DD + n], s0);
                    atomicAdd(&g_vsum[b * DD + n + 1], s1);
                }
            }
        }
    }
}

// ------------------------- histogram top-64 selection -------------------------
__global__ __launch_bounds__(256) void topk_radix()
{
    __shared__ uint32_t hist[4096];     // 16 KB
    __shared__ float    cv[2048];       // 8 KB
    __shared__ int      ci[2048];       // 8 KB
    __shared__ uint32_t gsum[256];
    __shared__ uint32_t s_thr, s_cnt;
    const int bh = blockIdx.x;
    const int tid = threadIdx.x;
#pragma unroll
    for (int i = 0; i < 16; i++) hist[tid + i * 256] = 0;
    if (tid == 0) s_cnt = 0;
    __syncthreads();

    const float* sp = g_sp + bh * SS;
    uint32_t ub[32];
#pragma unroll
    for (int i = 0; i < 32; i++) {
        ub[i] = __float_as_uint(sp[tid + i * 256]);
        atomicAdd(&hist[ub[i] >> 20], 1u);
    }
    __syncthreads();

    uint32_t gs = 0;
#pragma unroll
    for (int i = 0; i < 16; i++) gs += hist[tid * 16 + i];
    gsum[tid] = gs;
    __syncthreads();

    if (tid == 0) {
        uint32_t cum = 0;
        int g = 255;
        for (; g > 0; g--) {
            if (cum + gsum[g] >= NC) break;
            cum += gsum[g];
        }
        int b = g * 16 + 15;
        for (; b > g * 16; b--) {
            cum += hist[b];
            if (cum >= NC) break;
        }
        s_thr = (uint32_t)b;
    }
    __syncthreads();
    const uint32_t thr = s_thr;

#pragma unroll
    for (int i = 0; i < 32; i++) {
        if ((ub[i] >> 20) >= thr) {
            uint32_t p = atomicAdd(&s_cnt, 1u);
            if (p < 2048) { cv[p] = __uint_as_float(ub[i]); ci[p] = tid + i * 256; }
        }
    }
    __syncthreads();
    int C = (int)s_cnt;
    if (C > 2048) C = 2048;
    for (int c = tid; c < C; c += 256) {
        float myv = cv[c];
        int   myi = ci[c];
        int rank = 0;
        for (int j = 0; j < C; j++) {
            float o = cv[j];
            rank += (o > myv) || (o == myv && ci[j] < myi);
        }
        if (rank < NC) g_cand[bh * NC + rank] = myi;
    }
}

// ------------------------- exact fp32 recompute of candidate q rows ---------------
// warp u handles candidate grp*8+u; thread computes columns 2*lane, 2*lane+1
// via LDS.64 W reads (half the shared-load count of the scalar version).
__global__ __launch_bounds__(256)
void cand_refine(const float* __restrict__ X, const float* __restrict__ Wq,
                 const float* __restrict__ bq)
{
    __shared__ float sW[64][66];
    __shared__ float sX[8][64];
    __shared__ int   sS_[8];
    const int bh = blockIdx.x, grp = blockIdx.y;
    const int b = bh >> 3, h = bh & 7;
    const int tid = threadIdx.x;
    const int u = tid >> 5, lane = tid & 31;
    if (tid < 8) sS_[tid] = g_cand[bh * NC + grp * 8 + tid];
    float acc0 = 0.f, acc1 = 0.f;
    __syncthreads();
    for (int kc = 0; kc < 8; kc++) {
#pragma unroll
        for (int i = 0; i < 16; i++) {
            int idx = tid + i * 256;
            sW[idx >> 6][idx & 63] = Wq[(size_t)(kc * 64 + (idx >> 6)) * DD + h * HD + (idx & 63)];
        }
#pragma unroll
        for (int i = 0; i < 2; i++) {
            int idx = tid + i * 256;
            sX[idx >> 6][idx & 63] = X[((size_t)b * SS + sS_[idx >> 6]) * DD + kc * 64 + (idx & 63)];
        }
        __syncthreads();
#pragma unroll
        for (int k = 0; k < 64; k++) {
            float xv = sX[u][k];
            float2 wv = *(const float2*)&sW[k][lane * 2];
            acc0 = fmaf(xv, wv.x, acc0);
            acc1 = fmaf(xv, wv.y, acc1);
        }
        __syncthreads();
    }
    acc0 += bq[h * HD + lane * 2];
    acc1 += bq[h * HD + lane * 2 + 1];
    const int cu = bh * NC + grp * 8 + u;
    g_cq[cu * HD + lane * 2]     = acc0;
    g_cq[cu * HD + lane * 2 + 1] = acc1;
    float ss = acc0 * acc0 + acc1 * acc1;
#pragma unroll
    for (int off = 16; off > 0; off >>= 1) ss += __shfl_xor_sync(0xffffffffu, ss, off);
    if (lane == 0) g_csp[cu] = ss;
}

// ------------------------- exact top-45 among candidates -------------------------
__global__ __launch_bounds__(64) void final_sel()
{
    __shared__ float vv[NC];
    __shared__ int   ssd[NC];
    __shared__ int   slot[UU];
    const int bh = blockIdx.x;
    const int tid = threadIdx.x;
    float myv = g_csp[bh * NC + tid];
    int   mys = g_cand[bh * NC + tid];
    vv[tid] = myv; ssd[tid] = mys;
    __syncthreads();
    int rank = 0;
#pragma unroll
    for (int j = 0; j < NC; j++) {
        float o = vv[j];
        if (o > myv || (o == myv && ssd[j] < mys)) rank++;
    }
    if (rank < UU) { g_top[bh * UU + rank] = mys; slot[rank] = tid; }
    __syncthreads();
    for (int u = 0; u < UU; u++) {
        int c = slot[u];
        g_selq[(bh * UU + u) * HD + tid] = g_cq[(bh * NC + c) * HD + tid];
    }
}

// ------------------------- tensor-core flash attention (split-K over S) -----------
__global__ __launch_bounds__(256)
void attn_mma()
{
    __shared__ __align__(16) uint8_t sQ[48 * 128];    // bf16 swizzled
    __shared__ __align__(16) uint8_t sKV[64 * 128];   // K then V (bf16 swizzled)
    __shared__ __align__(16) uint8_t sPb[48 * 128];   // P bf16 swizzled
    __shared__ float sS[48][66];                      // raw scores fp32
    __shared__ float sm[48], sl[48], salpha[48];

    const int bh = blockIdx.x, sp = blockIdx.y;
    const int tid = threadIdx.x;
    const int lane = tid & 31, w = tid >> 5;
    const uint32_t qb = (uint32_t)__cvta_generic_to_shared(sQ);
    const uint32_t kb = (uint32_t)__cvta_generic_to_shared(sKV);
    const uint32_t pbm = (uint32_t)__cvta_generic_to_shared(sPb);

    for (int c = tid; c < 384; c += 256) {
        int r = c >> 3, u = c & 7;
        uint4 val = make_uint4(0, 0, 0, 0);
        if (r < UU) {
            const float* src = g_selq + ((size_t)bh * UU + r) * HD + u * 8;
            float4 f0 = *(const float4*)src;
            float4 f1 = *(const float4*)(src + 4);
            val.x = pk(f0.x * 0.125f, f0.y * 0.125f);
            val.y = pk(f0.z * 0.125f, f0.w * 0.125f);
            val.z = pk(f1.x * 0.125f, f1.y * 0.125f);
            val.w = pk(f1.z * 0.125f, f1.w * 0.125f);
        }
        *(uint4*)(sQ + r * 128 + ((u ^ (r & 7)) * 16)) = val;
    }
    if (tid < 48) { sm[tid] = -INFINITY; sl[tid] = 0.f; }

    float acc[3][4];
#pragma unroll
    for (int mt = 0; mt < 3; mt++)
#pragma unroll
        for (int c = 0; c < 4; c++) acc[mt][c] = 0.f;

    const __nv_bfloat16* kvK = g_k + ((size_t)bh * SS + sp * CHUNK) * HD;
    const __nv_bfloat16* kvV = g_v + ((size_t)bh * SS + sp * CHUNK) * HD;

    const int ro = lane & 15, ch2 = (lane >> 4) & 1;
    const int g = lane >> 2, tg = lane & 3;

    for (int t = 0; t < 8; t++) {
        __syncthreads();
        for (int c = tid; c < 512; c += 256) {
            int r = c >> 3, u = c & 7;
            uint4 val = *(const uint4*)(kvK + ((size_t)(t * 64 + r)) * HD + u * 8);
            *(uint4*)(sKV + r * 128 + ((u ^ (r & 7)) * 16)) = val;
        }
        __syncthreads();

        float Cr[3][4];
#pragma unroll
        for (int mt = 0; mt < 3; mt++)
#pragma unroll
            for (int c = 0; c < 4; c++) Cr[mt][c] = 0.f;
#pragma unroll
        for (int ks = 0; ks < 4; ks++) {
            uint32_t br[4];
            {
                int row = (w >> 1) * 16 + ro;
                ldsm4(br[0], br[1], br[2], br[3],
                      kb + row * 128 + (((ks * 2 + ch2) ^ (row & 7)) * 16));
            }
            uint32_t b0 = br[w & 1], b1 = br[(w & 1) + 2];
#pragma unroll
            for (int mt = 0; mt < 3; mt++) {
                uint32_t a[4];
                int row = mt * 16 + ro;
                ldsm4(a[0], a[1], a[2], a[3],
                      qb + row * 128 + (((ks * 2 + ch2) ^ (row & 7)) * 16));
                mma16816(Cr[mt], a, b0, b1);
            }
        }
#pragma unroll
        for (int mt = 0; mt < 3; mt++) {
            int col = w * 8 + tg * 2;
            sS[mt * 16 + g][col]     = Cr[mt][0];
            sS[mt * 16 + g][col + 1] = Cr[mt][1];
            sS[mt * 16 + g + 8][col]     = Cr[mt][2];
            sS[mt * 16 + g + 8][col + 1] = Cr[mt][3];
        }
        __syncthreads();

        for (int c = tid; c < 512; c += 256) {
            int r = c >> 3, u = c & 7;
            uint4 val = *(const uint4*)(kvV + ((size_t)(t * 64 + r)) * HD + u * 8);
            *(uint4*)(sKV + r * 128 + ((u ^ (r & 7)) * 16)) = val;
        }
        if (tid < 192) {
            int r = tid >> 2, qt = tid & 3;
            float mx = -INFINITY;
#pragma unroll
            for (int j = 0; j < 16; j++) mx = fmaxf(mx, sS[r][qt * 16 + j]);
            mx = fmaxf(mx, __shfl_xor_sync(0xffffffffu, mx, 1));
            mx = fmaxf(mx, __shfl_xor_sync(0xffffffffu, mx, 2));
            if (qt == 0) {
                float mnew = fmaxf(sm[r], mx);
                salpha[r] = __expf(sm[r] - mnew);
                sm[r] = mnew;
            }
        }
        __syncthreads();

#pragma unroll
        for (int mt = 0; mt < 3; mt++) {
            float a0 = salpha[mt * 16 + g];
            float a1 = salpha[mt * 16 + g + 8];
            acc[mt][0] *= a0; acc[mt][1] *= a0;
            acc[mt][2] *= a1; acc[mt][3] *= a1;
        }
        if (tid < 192) {
            int r = tid >> 2, qt = tid & 3;
            float mr = sm[r];
            float e[16], ls = 0.f;
#pragma unroll
            for (int j = 0; j < 16; j++) {
                e[j] = __expf(sS[r][qt * 16 + j] - mr);
                ls += e[j];
            }
            uint4 v0, v1;
            v0.x = pk(e[0], e[1]);   v0.y = pk(e[2], e[3]);
            v0.z = pk(e[4], e[5]);   v0.w = pk(e[6], e[7]);
            v1.x = pk(e[8], e[9]);   v1.y = pk(e[10], e[11]);
            v1.z = pk(e[12], e[13]); v1.w = pk(e[14], e[15]);
            *(uint4*)(sPb + r * 128 + (((qt * 2)     ^ (r & 7)) * 16)) = v0;
            *(uint4*)(sPb + r * 128 + (((qt * 2 + 1) ^ (r & 7)) * 16)) = v1;
            ls += __shfl_xor_sync(0xffffffffu, ls, 1);
            ls += __shfl_xor_sync(0xffffffffu, ls, 2);
            if (qt == 0) sl[r] = sl[r] * salpha[r] + ls;
        }
        __syncthreads();

#pragma unroll
        for (int ks = 0; ks < 4; ks++) {
            uint32_t br[4];
            {
                int row = ks * 16 + ro;
                ldsm4t(br[0], br[1], br[2], br[3],
                       kb + row * 128 + ((((w >> 1) * 2 + ch2) ^ (row & 7)) * 16));
            }
            uint32_t b0 = br[(w & 1) * 2], b1 = br[(w & 1) * 2 + 1];
#pragma unroll
            for (int mt = 0; mt < 3; mt++) {
                uint32_t a[4];
                int row = mt * 16 + ro;
                ldsm4(a[0], a[1], a[2], a[3],
                      pbm + row * 128 + (((ks * 2 + ch2) ^ (row & 7)) * 16));
                mma16816(acc[mt], a, b0, b1);
            }
        }
    }

    const int pbase = (bh * NSPLIT + sp) * UU;
    if (tid < UU) { g_pm[pbase + tid] = sm[tid]; g_pl[pbase + tid] = sl[tid]; }
#pragma unroll
    for (int mt = 0; mt < 3; mt++) {
        int q0 = mt * 16 + g, q1 = q0 + 8;
        int d = w * 8 + tg * 2;
        if (q0 < UU)
            *(float2*)(g_pacc + ((size_t)(pbase + q0)) * HD + d) = make_float2(acc[mt][0], acc[mt][1]);
        if (q1 < UU)
            *(float2*)(g_pacc + ((size_t)(pbase + q1)) * HD + d) = make_float2(acc[mt][2], acc[mt][3]);
    }
}

// ------------------------- fused split-K merge + output correction ----------------
// Threads 0-63 merge the NSPLIT partials into delta[] (same fp32 order as the
// old merge_kernel); all 512 threads then apply the Wo correction. Saves the
// g_selctx round-trip and one launch.
__global__ __launch_bounds__(512)
void merge_corr(const float* __restrict__ Wo, const float* __restrict__ bv,
                float* __restrict__ out)
{
    __shared__ float delta[64];
    __shared__ int ssel;
    const int bh = blockIdx.x, u = blockIdx.y;
    const int b = bh >> 3, h = bh & 7;
    const int tid = threadIdx.x;
    if (tid == 0) ssel = g_top[bh * UU + u];
    if (tid < 64) {
        const int d = tid;
        float M = -INFINITY;
#pragma unroll
        for (int i = 0; i < NSPLIT; i++)
            M = fmaxf(M, g_pm[(bh * NSPLIT + i) * UU + u]);
        float L = 0.f, ctx = 0.f;
        for (int i = 0; i < NSPLIT; i++) {
            int pi = (bh * NSPLIT + i) * UU + u;
            float w = __expf(g_pm[pi] - M);
            L += g_pl[pi] * w;
            ctx += g_pacc[(size_t)pi * HD + d] * w;
        }
        delta[d] = ctx / L - (g_vsum[bh * HD + d] * (1.f / SS) + bv[h * HD + d]);
    }
    __syncthreads();
    const int s = ssel;
    float a = 0.f;
#pragma unroll
    for (int d = 0; d < 64; d++)
        a = fmaf(delta[d], Wo[(size_t)(h * HD + d) * DD + tid], a);
    atomicAdd(out + ((size_t)b * SS + s) * DD + tid, a);
}

// ------------------------- output base + broadcast -------------------------
__global__ __launch_bounds__(512)
void base_kernel(const float* __restrict__ Wo, const float* __restrict__ bo,
                 const float* __restrict__ bv)
{
    __shared__ float vm[DD];
    const int b = blockIdx.x;
    const int n = threadIdx.x;
    vm[n] = g_vsum[b * DD + n] * (1.f / SS) + bv[n];
    __syncthreads();
    float a = bo[n];
    for (int kk = 0; kk < DD; kk++)
        a = fmaf(vm[kk], Wo[(size_t)kk * DD + n], a);
    g_base[b * DD + n] = a;
}

__global__ __launch_bounds__(256) void bcast_kernel(float* __restrict__ out)
{
    __shared__ float4 bs[128];
    const int row0 = blockIdx.x * 16;
    const int b = row0 >> 13;
    if (threadIdx.x < 128)
        bs[threadIdx.x] = ((const float4*)(g_base + b * DD))[threadIdx.x];
    __syncthreads();
    float4* o = (float4*)out + (size_t)row0 * 128;
    for (int i = threadIdx.x; i < 16 * 128; i += 256)
        o[i] = bs[i & 127];
}

// ------------------------- launch -------------------------
extern "C" void kernel_launch(void* const* d_in, const int* in_sizes, int n_in,
                              void* d_out, int out_size)
{
    (void)in_sizes; (void)n_in; (void)out_size;
    const float* x  = (const float*)d_in[0];
    const float* Wq = (const float*)d_in[1];
    const float* bq = (const float*)d_in[2];
    const float* Wk = (const float*)d_in[3];
    const float* bk = (const float*)d_in[4];
    const float* Wv = (const float*)d_in[5];
    const float* bv = (const float*)d_in[6];
    const float* Wo = (const float*)d_in[7];
    const float* bo = (const float*)d_in[8];
    float* out = (float*)d_out;

    cvt_all<<<18176, 256>>>(x, Wq, Wk, Wv);
    proj_all<<<dim3(256, 12), 256>>>(bq, bk, bv);
    topk_radix<<<BH, 256>>>();
    cand_refine<<<dim3(BH, NC / 8), 256>>>(x, Wq, bq);
    final_sel<<<BH, 64>>>();
    attn_mma<<<dim3(BH, NSPLIT), 256>>>();
    base_kernel<<<BB, DD>>>(Wo, bo, bv);
    bcast_kernel<<<BB * SS / 16, 256>>>(out);
    merge_corr<<<dim3(BH, UU), 512>>>(Wo, bv, out);
}

// round 14
// speedup vs baseline: 1.1113x; 1.0295x over previous
#include <cuda_runtime.h>
#include <cuda_bf16.h>
#include <math.h>
#include <stdint.h>

// Problem constants (fixed by setup_inputs)
#define BB 4
#define SS 8192
#define DD 512
#define HH 8
#define HD 64
#define BH 32      // B*H
#define UU 45      // int(5*ln(8193)) = 45 selected queries per (b,h)
#define NC 64      // candidate count for exact refinement
#define NSPLIT 16
#define CHUNK 512  // SS / NSPLIT

// ------------------------- device scratch -------------------------
static __device__ __align__(16) __nv_bfloat16 g_xb[(size_t)BB*SS*DD];  // 32 MB bf16 x
static __device__ __align__(16) __nv_bfloat16 g_wq[DD*DD];
static __device__ __align__(16) __nv_bfloat16 g_wk[DD*DD];
static __device__ __align__(16) __nv_bfloat16 g_wv[DD*DD];
static __device__ __align__(16) __nv_bfloat16 g_k[(size_t)BH*SS*HD];   // 32 MB [bh][s][d]
static __device__ __align__(16) __nv_bfloat16 g_v[(size_t)BH*SS*HD];   // 32 MB [bh][s][d]
static __device__ float g_sp[BH*SS];                               // approx ||q||^2
static __device__ int   g_cand[BH*NC];
static __device__ __align__(16) float g_cq[BH*NC*HD];              // exact q rows (atomic split-K)
static __device__ int   g_top[BH*UU];
static __device__ __align__(16) float g_selq[BH*UU*HD];
static __device__ float g_selctx[BH*UU*HD];
static __device__ float g_vsum[BB*DD];                             // sum over S of v (no bias)
static __device__ __align__(16) float g_base[BB*DD];
static __device__ float g_pm[BH*NSPLIT*UU];
static __device__ float g_pl[BH*NSPLIT*UU];
static __device__ __align__(16) float g_pacc[(size_t)BH*NSPLIT*UU*HD];

// pack two floats to bf16x2 (lo -> bits[15:0], hi -> bits[31:16])
__device__ __forceinline__ uint32_t pk(float lo, float hi) {
    uint32_t r;
    asm("cvt.rn.bf16x2.f32 %0, %1, %2;" : "=r"(r) : "f"(hi), "f"(lo));
    return r;
}

__device__ __forceinline__ void ldsm4(uint32_t& r0, uint32_t& r1, uint32_t& r2,
                                      uint32_t& r3, uint32_t addr) {
    asm volatile("ldmatrix.sync.aligned.m8n8.x4.shared.b16 {%0,%1,%2,%3}, [%4];"
                 : "=r"(r0), "=r"(r1), "=r"(r2), "=r"(r3) : "r"(addr));
}
__device__ __forceinline__ void ldsm4t(uint32_t& r0, uint32_t& r1, uint32_t& r2,
                                       uint32_t& r3, uint32_t addr) {
    asm volatile("ldmatrix.sync.aligned.m8n8.x4.trans.shared.b16 {%0,%1,%2,%3}, [%4];"
                 : "=r"(r0), "=r"(r1), "=r"(r2), "=r"(r3) : "r"(addr));
}
__device__ __forceinline__ void mma16816(float* c, const uint32_t* a,
                                         uint32_t b0, uint32_t b1) {
    asm volatile(
        "mma.sync.aligned.m16n8k16.row.col.f32.bf16.bf16.f32 "
        "{%0,%1,%2,%3}, {%4,%5,%6,%7}, {%8,%9}, {%0,%1,%2,%3};\n"
        : "+f"(c[0]), "+f"(c[1]), "+f"(c[2]), "+f"(c[3])
        : "r"(a[0]), "r"(a[1]), "r"(a[2]), "r"(a[3]), "r"(b0), "r"(b1));
}

// ------------------------- fused converter + zero -------------------------
__global__ __launch_bounds__(256)
void cvt_all(const float* __restrict__ x,
             const float* __restrict__ Wq, const float* __restrict__ Wk,
             const float* __restrict__ Wv)
{
    const int blk = blockIdx.x;
    const int tid = threadIdx.x;
    if (blk < 16384) {
        int i = blk * 256 + tid;
        float4 v = ((const float4*)x)[i];
        uint2 o;
        o.x = pk(v.x, v.y);
        o.y = pk(v.z, v.w);
        ((uint2*)g_xb)[i] = o;
    } else if (blk < 17152) {
        int idx = blk - 16384;
        int w = idx >> 8;          // 0..2
        int i = (idx & 255) * 256 + tid;
        const float* src = (w == 0) ? Wq : (w == 1) ? Wk : Wv;
        __nv_bfloat16* dst = (w == 0) ? g_wq : (w == 1) ? g_wk : g_wv;
        float4 v = ((const float4*)src)[i];
        uint2 o;
        o.x = pk(v.x, v.y);
        o.y = pk(v.z, v.w);
        ((uint2*)dst)[i] = o;
    } else {
        int j = (blk - 17152) * 256 + tid;
        g_sp[j] = 0.f;
        if (j < BB * DD) g_vsum[j] = 0.f;
        if (j < BH * NC * HD) g_cq[j] = 0.f;
    }
}

// ------------------------- fused bf16 tensor-core projection GEMM -----------------
// Round-11 anchor: tile 128x128, BK=32, 8 warps (2M x 4N), warp tile 64x32,
// double-buffered register-staged smem, 2 CTAs/SM.
// grid (256, 12): which = y>>2 (0=q,1=k,2=v), n0=(y&3)*128.
__global__ __launch_bounds__(256)
void proj_all(const float* __restrict__ bq, const float* __restrict__ bk,
              const float* __restrict__ bv)
{
    __shared__ __align__(16) uint32_t sAm[2][2048];   // 8 KB each
    __shared__ __align__(16) uint32_t sBm[2][2048];   // 8 KB each

    const int tid = threadIdx.x;
    const int lane = tid & 31, wid = tid >> 5;
    const int mwarp = wid >> 2, nwarp = wid & 3;
    const int which = blockIdx.y >> 2;
    const int m0 = blockIdx.x * 128, n0 = (blockIdx.y & 3) * 128;

    const __nv_bfloat16* __restrict__ X = g_xb;
    const __nv_bfloat16* __restrict__ W = (which == 0) ? g_wq : (which == 1) ? g_wk : g_wv;
    const float* __restrict__ bias = (which == 0) ? bq : (which == 1) ? bk : bv;

    const int rowA = tid >> 1, halfA = tid & 1;
    const int rowB = tid >> 3, segB = tid & 7;
    const __nv_bfloat16* gA = X + (size_t)(m0 + rowA) * DD + halfA * 16;
    const __nv_bfloat16* gB = W + (size_t)rowB * DD + n0 + segB * 16;

    const int usA = (rowA >> 1) & 3;
    const int aOff0 = rowA * 16 + ((halfA * 2)     ^ usA) * 4;
    const int aOff1 = rowA * 16 + ((halfA * 2 + 1) ^ usA) * 4;
    const int usB = rowB & 7;
    const int bOff0 = rowB * 64 + ((segB * 2)     ^ usB) * 4;
    const int bOff1 = rowB * 64 + ((segB * 2 + 1) ^ usB) * 4;

    uint4 a0, a1, b0, b1;
    a0 = *(const uint4*)(gA);
    a1 = *(const uint4*)(gA + 8);
    b0 = *(const uint4*)(gB);
    b1 = *(const uint4*)(gB + 8);

    float acc[4][4][4];
#pragma unroll
    for (int mi = 0; mi < 4; mi++)
#pragma unroll
        for (int ni = 0; ni < 4; ni++)
#pragma unroll
            for (int c = 0; c < 4; c++) acc[mi][ni][c] = 0.f;

    const uint32_t aBase = (uint32_t)__cvta_generic_to_shared(&sAm[0][0]);
    const uint32_t bBase = (uint32_t)__cvta_generic_to_shared(&sBm[0][0]);

    const int ro  = lane & 15;
    const int ch2 = (lane >> 4) & 1;
    const int rs2 = (ro >> 1) & 3;
    const int rs7 = ro & 7;

    auto stage = [&](int buf) {
        *(uint4*)&sAm[buf][aOff0] = a0;
        *(uint4*)&sAm[buf][aOff1] = a1;
        *(uint4*)&sBm[buf][bOff0] = b0;
        *(uint4*)&sBm[buf][bOff1] = b1;
    };

    stage(0);
    __syncthreads();

    for (int chn = 0; chn < 16; chn++) {
        if (chn < 15) {
            const __nv_bfloat16* pA = gA + (chn + 1) * 32;
            const __nv_bfloat16* pB = gB + (size_t)(chn + 1) * 32 * DD;
            a0 = *(const uint4*)(pA);
            a1 = *(const uint4*)(pA + 8);
            b0 = *(const uint4*)(pB);
            b1 = *(const uint4*)(pB + 8);
        }
        {
            const uint32_t ab = aBase + (chn & 1) * 8192;
            const uint32_t bb = bBase + (chn & 1) * 8192;
#pragma unroll
            for (int kblk = 0; kblk < 2; kblk++) {
                uint32_t af[4][4];
#pragma unroll
                for (int mi = 0; mi < 4; mi++) {
                    int row = mwarp * 64 + mi * 16 + ro;
                    int u = (kblk * 2 + ch2) ^ rs2;
                    ldsm4(af[mi][0], af[mi][1], af[mi][2], af[mi][3],
                          ab + (row * 16 + u * 4) * 4);
                }
                uint32_t bf[2][4];
#pragma unroll
                for (int np = 0; np < 2; np++) {
                    int row = kblk * 16 + ro;
                    int u = (nwarp * 4 + np * 2 + ch2) ^ rs7;
                    ldsm4t(bf[np][0], bf[np][1], bf[np][2], bf[np][3],
                           bb + (row * 64 + u * 4) * 4);
                }
#pragma unroll
                for (int mi = 0; mi < 4; mi++)
#pragma unroll
                    for (int ni = 0; ni < 4; ni++)
                        mma16816(acc[mi][ni], af[mi],
                                 bf[ni >> 1][(ni & 1) * 2], bf[ni >> 1][(ni & 1) * 2 + 1]);
            }
        }
        if (chn < 15) stage((chn + 1) & 1);
        __syncthreads();
    }

    const int g = lane >> 2, tig = lane & 3;

    float bn[4][2];
#pragma unroll
    for (int ni = 0; ni < 4; ni++) {
        int n = n0 + nwarp * 32 + ni * 8 + tig * 2;
        bn[ni][0] = bias[n];
        bn[ni][1] = bias[n + 1];
    }

    if (which == 0) {
        const int h = (n0 + nwarp * 32) >> 6;
#pragma unroll
        for (int mi = 0; mi < 4; mi++) {
            int m = m0 + mwarp * 64 + mi * 16 + g;
            int b = m >> 13;
            int s = m & (SS - 1);
            float ss0 = 0.f, ss1 = 0.f;
#pragma unroll
            for (int ni = 0; ni < 4; ni++) {
                float c0 = acc[mi][ni][0] + bn[ni][0];
                float c1 = acc[mi][ni][1] + bn[ni][1];
                float c2 = acc[mi][ni][2] + bn[ni][0];
                float c3 = acc[mi][ni][3] + bn[ni][1];
                ss0 = fmaf(c0, c0, fmaf(c1, c1, ss0));
                ss1 = fmaf(c2, c2, fmaf(c3, c3, ss1));
            }
            ss0 += __shfl_xor_sync(0xffffffffu, ss0, 1);
            ss0 += __shfl_xor_sync(0xffffffffu, ss0, 2);
            ss1 += __shfl_xor_sync(0xffffffffu, ss1, 1);
            ss1 += __shfl_xor_sync(0xffffffffu, ss1, 2);
            if (tig == 0) {
                atomicAdd(&g_sp[(b * HH + h) * SS + s], ss0);
                atomicAdd(&g_sp[(b * HH + h) * SS + s + 8], ss1);
            }
        }
    } else {
        __nv_bfloat16* __restrict__ dst = (which == 1) ? g_k : g_v;
#pragma unroll
        for (int mi = 0; mi < 4; mi++) {
            int m = m0 + mwarp * 64 + mi * 16 + g;
            int b = m >> 13;
            int s = m & (SS - 1);
#pragma unroll
            for (int ni = 0; ni < 4; ni++) {
                int n = n0 + nwarp * 32 + ni * 8 + tig * 2;
                int h = n >> 6, d = n & 63;
                uint32_t lo = pk(acc[mi][ni][0] + bn[ni][0], acc[mi][ni][1] + bn[ni][1]);
                uint32_t hi = pk(acc[mi][ni][2] + bn[ni][0], acc[mi][ni][3] + bn[ni][1]);
                *(uint32_t*)(dst + (((size_t)(b * HH + h)) * SS + s) * HD + d)     = lo;
                *(uint32_t*)(dst + (((size_t)(b * HH + h)) * SS + s + 8) * HD + d) = hi;
            }
        }
        if (which == 2) {
            const int b = m0 >> 13;
#pragma unroll
            for (int ni = 0; ni < 4; ni++) {
                float s0 = 0.f, s1 = 0.f;
#pragma unroll
                for (int mi = 0; mi < 4; mi++) {
                    s0 += acc[mi][ni][0] + acc[mi][ni][2];
                    s1 += acc[mi][ni][1] + acc[mi][ni][3];
                }
#pragma unroll
                for (int off = 4; off <= 16; off <<= 1) {
                    s0 += __shfl_xor_sync(0xffffffffu, s0, off);
                    s1 += __shfl_xor_sync(0xffffffffu, s1, off);
                }
                if (g == 0) {
                    int n = n0 + nwarp * 32 + ni * 8 + tig * 2;
                    atomicAdd(&g_vsum[b * DD + n], s0);
                    atomicAdd(&g_vsum[b * DD + n + 1], s1);
                }
            }
        }
    }
}

// ------------------------- histogram top-64 selection -------------------------
__global__ __launch_bounds__(256) void topk_radix()
{
    __shared__ uint32_t hist[4096];     // 16 KB
    __shared__ float    cv[2048];       // 8 KB
    __shared__ int      ci[2048];       // 8 KB
    __shared__ uint32_t gsum[256];
    __shared__ uint32_t s_thr, s_cnt;
    const int bh = blockIdx.x;
    const int tid = threadIdx.x;
#pragma unroll
    for (int i = 0; i < 16; i++) hist[tid + i * 256] = 0;
    if (tid == 0) s_cnt = 0;
    __syncthreads();

    const float* sp = g_sp + bh * SS;
    uint32_t ub[32];
#pragma unroll
    for (int i = 0; i < 32; i++) {
        ub[i] = __float_as_uint(sp[tid + i * 256]);
        atomicAdd(&hist[ub[i] >> 20], 1u);
    }
    __syncthreads();

    uint32_t gs = 0;
#pragma unroll
    for (int i = 0; i < 16; i++) gs += hist[tid * 16 + i];
    gsum[tid] = gs;
    __syncthreads();

    if (tid == 0) {
        uint32_t cum = 0;
        int g = 255;
        for (; g > 0; g--) {
            if (cum + gsum[g] >= NC) break;
            cum += gsum[g];
        }
        int b = g * 16 + 15;
        for (; b > g * 16; b--) {
            cum += hist[b];
            if (cum >= NC) break;
        }
        s_thr = (uint32_t)b;
    }
    __syncthreads();
    const uint32_t thr = s_thr;

#pragma unroll
    for (int i = 0; i < 32; i++) {
        if ((ub[i] >> 20) >= thr) {
            uint32_t p = atomicAdd(&s_cnt, 1u);
            if (p < 2048) { cv[p] = __uint_as_float(ub[i]); ci[p] = tid + i * 256; }
        }
    }
    __syncthreads();
    int C = (int)s_cnt;
    if (C > 2048) C = 2048;
    for (int c = tid; c < C; c += 256) {
        float myv = cv[c];
        int   myi = ci[c];
        int rank = 0;
        for (int j = 0; j < C; j++) {
            float o = cv[j];
            rank += (o > myv) || (o == myv && ci[j] < myi);
        }
        if (rank < NC) g_cand[bh * NC + rank] = myi;
    }
}

// ------------------------- exact fp32 recompute of candidate q rows (split-K) -----
// grid (BH, NC/8, 2): block z=ks covers k in [ks*256, ks*256+256) (4 chunks of 64).
// Partials accumulate into pre-zeroed g_cq via atomicAdd; ks==0 carries the bias.
__global__ __launch_bounds__(256)
void cand_refine(const float* __restrict__ X, const float* __restrict__ Wq,
                 const float* __restrict__ bq)
{
    __shared__ float sW[64][66];
    __shared__ float sX[8][64];
    __shared__ int   sS_[8];
    const int bh = blockIdx.x, grp = blockIdx.y, ks = blockIdx.z;
    const int b = bh >> 3, h = bh & 7;
    const int tid = threadIdx.x;
    const int u = tid >> 5, lane = tid & 31;
    if (tid < 8) sS_[tid] = g_cand[bh * NC + grp * 8 + tid];
    float acc0 = (ks == 0) ? bq[h * HD + lane * 2]     : 0.f;
    float acc1 = (ks == 0) ? bq[h * HD + lane * 2 + 1] : 0.f;
    __syncthreads();
    for (int kc = ks * 4; kc < ks * 4 + 4; kc++) {
#pragma unroll
        for (int i = 0; i < 16; i++) {
            int idx = tid + i * 256;
            sW[idx >> 6][idx & 63] = Wq[(size_t)(kc * 64 + (idx >> 6)) * DD + h * HD + (idx & 63)];
        }
#pragma unroll
        for (int i = 0; i < 2; i++) {
            int idx = tid + i * 256;
            sX[idx >> 6][idx & 63] = X[((size_t)b * SS + sS_[idx >> 6]) * DD + kc * 64 + (idx & 63)];
        }
        __syncthreads();
#pragma unroll
        for (int k = 0; k < 64; k++) {
            float xv = sX[u][k];
            float2 wv = *(const float2*)&sW[k][lane * 2];
            acc0 = fmaf(xv, wv.x, acc0);
            acc1 = fmaf(xv, wv.y, acc1);
        }
        __syncthreads();
    }
    const int cu = bh * NC + grp * 8 + u;
    atomicAdd(&g_cq[cu * HD + lane * 2], acc0);
    atomicAdd(&g_cq[cu * HD + lane * 2 + 1], acc1);
}

// ------------------------- exact top-45 among candidates (computes sumsq) ---------
__global__ __launch_bounds__(64) void final_sel()
{
    __shared__ float sq2[NC][65];   // padded: conflict-free row reads
    __shared__ float vv[NC];
    __shared__ int   ssd[NC];
    __shared__ int   slot[UU];
    const int bh = blockIdx.x;
    const int tid = threadIdx.x;
    for (int i = tid; i < NC * 64; i += 64)
        sq2[i >> 6][i & 63] = g_cq[bh * NC * HD + i];
    ssd[tid] = g_cand[bh * NC + tid];
    __syncthreads();
    float ss = 0.f;
#pragma unroll
    for (int d = 0; d < 64; d++) {
        float v = sq2[tid][d];
        ss = fmaf(v, v, ss);
    }
    vv[tid] = ss;
    __syncthreads();
    float myv = vv[tid];
    int   mys = ssd[tid];
    int rank = 0;
#pragma unroll
    for (int j = 0; j < NC; j++) {
        float o = vv[j];
        if (o > myv || (o == myv && ssd[j] < mys)) rank++;
    }
    if (rank < UU) { g_top[bh * UU + rank] = mys; slot[rank] = tid; }
    __syncthreads();
    for (int u = 0; u < UU; u++) {
        int c = slot[u];
        g_selq[(bh * UU + u) * HD + tid] = sq2[c][tid];
    }
}

// ------------------------- tensor-core flash attention (split-K over S) -----------
__global__ __launch_bounds__(256)
void attn_mma()
{
    __shared__ __align__(16) uint8_t sQ[48 * 128];    // bf16 swizzled
    __shared__ __align__(16) uint8_t sKV[64 * 128];   // K then V (bf16 swizzled)
    __shared__ __align__(16) uint8_t sPb[48 * 128];   // P bf16 swizzled
    __shared__ float sS[48][66];                      // raw scores fp32
    __shared__ float sm[48], sl[48], salpha[48];

    const int bh = blockIdx.x, sp = blockIdx.y;
    const int tid = threadIdx.x;
    const int lane = tid & 31, w = tid >> 5;
    const uint32_t qb = (uint32_t)__cvta_generic_to_shared(sQ);
    const uint32_t kb = (uint32_t)__cvta_generic_to_shared(sKV);
    const uint32_t pbm = (uint32_t)__cvta_generic_to_shared(sPb);

    for (int c = tid; c < 384; c += 256) {
        int r = c >> 3, u = c & 7;
        uint4 val = make_uint4(0, 0, 0, 0);
        if (r < UU) {
            const float* src = g_selq + ((size_t)bh * UU + r) * HD + u * 8;
            float4 f0 = *(const float4*)src;
            float4 f1 = *(const float4*)(src + 4);
            val.x = pk(f0.x * 0.125f, f0.y * 0.125f);
            val.y = pk(f0.z * 0.125f, f0.w * 0.125f);
            val.z = pk(f1.x * 0.125f, f1.y * 0.125f);
            val.w = pk(f1.z * 0.125f, f1.w * 0.125f);
        }
        *(uint4*)(sQ + r * 128 + ((u ^ (r & 7)) * 16)) = val;
    }
    if (tid < 48) { sm[tid] = -INFINITY; sl[tid] = 0.f; }

    float acc[3][4];
#pragma unroll
    for (int mt = 0; mt < 3; mt++)
#pragma unroll
        for (int c = 0; c < 4; c++) acc[mt][c] = 0.f;

    const __nv_bfloat16* kvK = g_k + ((size_t)bh * SS + sp * CHUNK) * HD;
    const __nv_bfloat16* kvV = g_v + ((size_t)bh * SS + sp * CHUNK) * HD;

    const int ro = lane & 15, ch2 = (lane >> 4) & 1;
    const int g = lane >> 2, tg = lane & 3;

    for (int t = 0; t < 8; t++) {
        __syncthreads();
        for (int c = tid; c < 512; c += 256) {
            int r = c >> 3, u = c & 7;
            uint4 val = *(const uint4*)(kvK + ((size_t)(t * 64 + r)) * HD + u * 8);
            *(uint4*)(sKV + r * 128 + ((u ^ (r & 7)) * 16)) = val;
        }
        __syncthreads();

        float Cr[3][4];
#pragma unroll
        for (int mt = 0; mt < 3; mt++)
#pragma unroll
            for (int c = 0; c < 4; c++) Cr[mt][c] = 0.f;
#pragma unroll
        for (int ks = 0; ks < 4; ks++) {
            uint32_t br[4];
            {
                int row = (w >> 1) * 16 + ro;
                ldsm4(br[0], br[1], br[2], br[3],
                      kb + row * 128 + (((ks * 2 + ch2) ^ (row & 7)) * 16));
            }
            uint32_t b0 = br[w & 1], b1 = br[(w & 1) + 2];
#pragma unroll
            for (int mt = 0; mt < 3; mt++) {
                uint32_t a[4];
                int row = mt * 16 + ro;
                ldsm4(a[0], a[1], a[2], a[3],
                      qb + row * 128 + (((ks * 2 + ch2) ^ (row & 7)) * 16));
                mma16816(Cr[mt], a, b0, b1);
            }
        }
#pragma unroll
        for (int mt = 0; mt < 3; mt++) {
            int col = w * 8 + tg * 2;
            sS[mt * 16 + g][col]     = Cr[mt][0];
            sS[mt * 16 + g][col + 1] = Cr[mt][1];
            sS[mt * 16 + g + 8][col]     = Cr[mt][2];
            sS[mt * 16 + g + 8][col + 1] = Cr[mt][3];
        }
        __syncthreads();

        for (int c = tid; c < 512; c += 256) {
            int r = c >> 3, u = c & 7;
            uint4 val = *(const uint4*)(kvV + ((size_t)(t * 64 + r)) * HD + u * 8);
            *(uint4*)(sKV + r * 128 + ((u ^ (r & 7)) * 16)) = val;
        }
        if (tid < 192) {
            int r = tid >> 2, qt = tid & 3;
            float mx = -INFINITY;
#pragma unroll
            for (int j = 0; j < 16; j++) mx = fmaxf(mx, sS[r][qt * 16 + j]);
            mx = fmaxf(mx, __shfl_xor_sync(0xffffffffu, mx, 1));
            mx = fmaxf(mx, __shfl_xor_sync(0xffffffffu, mx, 2));
            if (qt == 0) {
                float mnew = fmaxf(sm[r], mx);
                salpha[r] = __expf(sm[r] - mnew);
                sm[r] = mnew;
            }
        }
        __syncthreads();

#pragma unroll
        for (int mt = 0; mt < 3; mt++) {
            float a0 = salpha[mt * 16 + g];
            float a1 = salpha[mt * 16 + g + 8];
            acc[mt][0] *= a0; acc[mt][1] *= a0;
            acc[mt][2] *= a1; acc[mt][3] *= a1;
        }
        if (tid < 192) {
            int r = tid >> 2, qt = tid & 3;
            float mr = sm[r];
            float e[16], ls = 0.f;
#pragma unroll
            for (int j = 0; j < 16; j++) {
                e[j] = __expf(sS[r][qt * 16 + j] - mr);
                ls += e[j];
            }
            uint4 v0, v1;
            v0.x = pk(e[0], e[1]);   v0.y = pk(e[2], e[3]);
            v0.z = pk(e[4], e[5]);   v0.w = pk(e[6], e[7]);
            v1.x = pk(e[8], e[9]);   v1.y = pk(e[10], e[11]);
            v1.z = pk(e[12], e[13]); v1.w = pk(e[14], e[15]);
            *(uint4*)(sPb + r * 128 + (((qt * 2)     ^ (r & 7)) * 16)) = v0;
            *(uint4*)(sPb + r * 128 + (((qt * 2 + 1) ^ (r & 7)) * 16)) = v1;
            ls += __shfl_xor_sync(0xffffffffu, ls, 1);
            ls += __shfl_xor_sync(0xffffffffu, ls, 2);
            if (qt == 0) sl[r] = sl[r] * salpha[r] + ls;
        }
        __syncthreads();

#pragma unroll
        for (int ks = 0; ks < 4; ks++) {
            uint32_t br[4];
            {
                int row = ks * 16 + ro;
                ldsm4t(br[0], br[1], br[2], br[3],
                       kb + row * 128 + ((((w >> 1) * 2 + ch2) ^ (row & 7)) * 16));
            }
            uint32_t b0 = br[(w & 1) * 2], b1 = br[(w & 1) * 2 + 1];
#pragma unroll
            for (int mt = 0; mt < 3; mt++) {
                uint32_t a[4];
                int row = mt * 16 + ro;
                ldsm4(a[0], a[1], a[2], a[3],
                      pbm + row * 128 + (((ks * 2 + ch2) ^ (row & 7)) * 16));
                mma16816(acc[mt], a, b0, b1);
            }
        }
    }

    const int pbase = (bh * NSPLIT + sp) * UU;
    if (tid < UU) { g_pm[pbase + tid] = sm[tid]; g_pl[pbase + tid] = sl[tid]; }
#pragma unroll
    for (int mt = 0; mt < 3; mt++) {
        int q0 = mt * 16 + g, q1 = q0 + 8;
        int d = w * 8 + tg * 2;
        if (q0 < UU)
            *(float2*)(g_pacc + ((size_t)(pbase + q0)) * HD + d) = make_float2(acc[mt][0], acc[mt][1]);
        if (q1 < UU)
            *(float2*)(g_pacc + ((size_t)(pbase + q1)) * HD + d) = make_float2(acc[mt][2], acc[mt][3]);
    }
}

// ------------------------- split-K merge -------------------------
__global__ __launch_bounds__(64) void merge_kernel()
{
    const int bh = blockIdx.x, u = blockIdx.y;
    const int d = threadIdx.x;
    float M = -INFINITY;
#pragma unroll
    for (int i = 0; i < NSPLIT; i++)
        M = fmaxf(M, g_pm[(bh * NSPLIT + i) * UU + u]);
    float L = 0.f, ctx = 0.f;
    for (int i = 0; i < NSPLIT; i++) {
        int pi = (bh * NSPLIT + i) * UU + u;
        float w = __expf(g_pm[pi] - M);
        L += g_pl[pi] * w;
        ctx += g_pacc[(size_t)pi * HD + d] * w;
    }
    g_selctx[(bh * UU + u) * HD + d] = ctx / L;
}

// ------------------------- output base, broadcast, corrections -------------------------
__global__ __launch_bounds__(512)
void base_kernel(const float* __restrict__ Wo, const float* __restrict__ bo,
                 const float* __restrict__ bv)
{
    __shared__ float vm[DD];
    const int b = blockIdx.x;
    const int n = threadIdx.x;
    vm[n] = g_vsum[b * DD + n] * (1.f / SS) + bv[n];
    __syncthreads();
    float a = bo[n];
    for (int kk = 0; kk < DD; kk++)
        a = fmaf(vm[kk], Wo[(size_t)kk * DD + n], a);
    g_base[b * DD + n] = a;
}

__global__ __launch_bounds__(256) void bcast_kernel(float* __restrict__ out)
{
    __shared__ float4 bs[128];
    const int row0 = blockIdx.x * 16;
    const int b = row0 >> 13;
    if (threadIdx.x < 128)
        bs[threadIdx.x] = ((const float4*)(g_base + b * DD))[threadIdx.x];
    __syncthreads();
    float4* o = (float4*)out + (size_t)row0 * 128;
    for (int i = threadIdx.x; i < 16 * 128; i += 256)
        o[i] = bs[i & 127];
}

__global__ __launch_bounds__(512)
void corr_kernel(const float* __restrict__ Wo, const float* __restrict__ bv,
                 float* __restrict__ out)
{
    __shared__ float delta[64];
    __shared__ int ssel;
    const int bh = blockIdx.x, u = blockIdx.y;
    const int b = bh >> 3, h = bh & 7;
    const int tid = threadIdx.x;
    if (tid == 0) ssel = g_top[bh * UU + u];
    if (tid < 64)
        delta[tid] = g_selctx[(bh * UU + u) * HD + tid]
                   - (g_vsum[bh * HD + tid] * (1.f / SS) + bv[h * HD + tid]);
    __syncthreads();
    const int s = ssel;
    float a = 0.f;
#pragma unroll
    for (int d = 0; d < 64; d++)
        a = fmaf(delta[d], Wo[(size_t)(h * HD + d) * DD + tid], a);
    atomicAdd(out + ((size_t)b * SS + s) * DD + tid, a);
}

// ------------------------- launch -------------------------
extern "C" void kernel_launch(void* const* d_in, const int* in_sizes, int n_in,
                              void* d_out, int out_size)
{
    (void)in_sizes; (void)n_in; (void)out_size;
    const float* x  = (const float*)d_in[0];
    const float* Wq = (const float*)d_in[1];
    const float* bq = (const float*)d_in[2];
    const float* Wk = (const float*)d_in[3];
    const float* bk = (const float*)d_in[4];
    const float* Wv = (const float*)d_in[5];
    const float* bv = (const float*)d_in[6];
    const float* Wo = (const float*)d_in[7];
    const float* bo = (const float*)d_in[8];
    float* out = (float*)d_out;

    cvt_all<<<18176, 256>>>(x, Wq, Wk, Wv);
    proj_all<<<dim3(256, 12), 256>>>(bq, bk, bv);
    topk_radix<<<BH, 256>>>();
    cand_refine<<<dim3(BH, NC / 8, 2), 256>>>(x, Wq, bq);
    final_sel<<<BH, 64>>>();
    attn_mma<<<dim3(BH, NSPLIT), 256>>>();
    merge_kernel<<<dim3(BH, UU), HD>>>();
    base_kernel<<<BB, DD>>>(Wo, bo, bv);
    bcast_kernel<<<BB * SS / 16, 256>>>(out);
    corr_kernel<<<dim3(BH, UU), DD>>>(Wo, bv, out);
}

// round 15
// speedup vs baseline: 1.1449x; 1.0302x over previous
#include <cuda_runtime.h>
#include <cuda_bf16.h>
#include <math.h>
#include <stdint.h>

// Problem constants (fixed by setup_inputs)
#define BB 4
#define SS 8192
#define DD 512
#define HH 8
#define HD 64
#define BH 32      // B*H
#define UU 45      // int(5*ln(8193)) = 45 selected queries per (b,h)
#define NC 64      // candidate count for exact refinement
#define NSPLIT 16
#define CHUNK 512  // SS / NSPLIT

// ------------------------- device scratch -------------------------
static __device__ __align__(16) __nv_bfloat16 g_xb[(size_t)BB*SS*DD];  // 32 MB bf16 x
static __device__ __align__(16) __nv_bfloat16 g_wq[DD*DD];
static __device__ __align__(16) __nv_bfloat16 g_wk[DD*DD];
static __device__ __align__(16) __nv_bfloat16 g_wv[DD*DD];
static __device__ __align__(16) __nv_bfloat16 g_k[(size_t)BH*SS*HD];   // 32 MB [bh][s][d]
static __device__ __align__(16) __nv_bfloat16 g_v[(size_t)BH*SS*HD];   // 32 MB [bh][s][d]
static __device__ float g_sp[BH*SS];                               // approx ||q||^2
static __device__ int   g_cand[BH*NC];
static __device__ __align__(16) float g_cq[BH*NC*HD];              // exact q rows (atomic split-K)
static __device__ int   g_top[BH*UU];
static __device__ __align__(16) float g_selq[BH*UU*HD];
static __device__ float g_selctx[BH*UU*HD];
static __device__ float g_vsum[BB*DD];                             // sum over S of v (no bias)
static __device__ __align__(16) float g_base[BB*DD];
static __device__ float g_pm[BH*NSPLIT*UU];
static __device__ float g_pl[BH*NSPLIT*UU];
static __device__ __align__(16) float g_pacc[(size_t)BH*NSPLIT*UU*HD];

// pack two floats to bf16x2 (lo -> bits[15:0], hi -> bits[31:16])
__device__ __forceinline__ uint32_t pk(float lo, float hi) {
    uint32_t r;
    asm("cvt.rn.bf16x2.f32 %0, %1, %2;" : "=r"(r) : "f"(hi), "f"(lo));
    return r;
}

__device__ __forceinline__ void ldsm4(uint32_t& r0, uint32_t& r1, uint32_t& r2,
                                      uint32_t& r3, uint32_t addr) {
    asm volatile("ldmatrix.sync.aligned.m8n8.x4.shared.b16 {%0,%1,%2,%3}, [%4];"
                 : "=r"(r0), "=r"(r1), "=r"(r2), "=r"(r3) : "r"(addr));
}
__device__ __forceinline__ void ldsm4t(uint32_t& r0, uint32_t& r1, uint32_t& r2,
                                       uint32_t& r3, uint32_t addr) {
    asm volatile("ldmatrix.sync.aligned.m8n8.x4.trans.shared.b16 {%0,%1,%2,%3}, [%4];"
                 : "=r"(r0), "=r"(r1), "=r"(r2), "=r"(r3) : "r"(addr));
}
__device__ __forceinline__ void mma16816(float* c, const uint32_t* a,
                                         uint32_t b0, uint32_t b1) {
    asm volatile(
        "mma.sync.aligned.m16n8k16.row.col.f32.bf16.bf16.f32 "
        "{%0,%1,%2,%3}, {%4,%5,%6,%7}, {%8,%9}, {%0,%1,%2,%3};\n"
        : "+f"(c[0]), "+f"(c[1]), "+f"(c[2]), "+f"(c[3])
        : "r"(a[0]), "r"(a[1]), "r"(a[2]), "r"(a[3]), "r"(b0), "r"(b1));
}
// L1-allocating async copy (16B). .ca keeps W tiles resident in L1 across CTAs.
__device__ __forceinline__ void cpa16(uint32_t dst, const void* src) {
    asm volatile("cp.async.ca.shared.global [%0], [%1], 16;\n" :: "r"(dst), "l"(src));
}

// ------------------------- fused converter + zero -------------------------
__global__ __launch_bounds__(256)
void cvt_all(const float* __restrict__ x,
             const float* __restrict__ Wq, const float* __restrict__ Wk,
             const float* __restrict__ Wv)
{
    const int blk = blockIdx.x;
    const int tid = threadIdx.x;
    if (blk < 16384) {
        int i = blk * 256 + tid;
        float4 v = ((const float4*)x)[i];
        uint2 o;
        o.x = pk(v.x, v.y);
        o.y = pk(v.z, v.w);
        ((uint2*)g_xb)[i] = o;
    } else if (blk < 17152) {
        int idx = blk - 16384;
        int w = idx >> 8;          // 0..2
        int i = (idx & 255) * 256 + tid;
        const float* src = (w == 0) ? Wq : (w == 1) ? Wk : Wv;
        __nv_bfloat16* dst = (w == 0) ? g_wq : (w == 1) ? g_wk : g_wv;
        float4 v = ((const float4*)src)[i];
        uint2 o;
        o.x = pk(v.x, v.y);
        o.y = pk(v.z, v.w);
        ((uint2*)dst)[i] = o;
    } else {
        int j = (blk - 17152) * 256 + tid;
        g_sp[j] = 0.f;
        if (j < BB * DD) g_vsum[j] = 0.f;
        if (j < BH * NC * HD) g_cq[j] = 0.f;
    }
}

// ------------------------- fused bf16 tensor-core projection GEMM -----------------
// Tile 128x128, BK=32, 8 warps (2M x 4N), warp tile 64x32. 3-stage cp.async.ca
// pipeline (2 chunks in flight), one barrier per chunk. Same swizzle/ldmatrix/mma
// math as the register-staged anchor -> bit-identical accumulation.
// grid (256, 12): which = y>>2 (0=q,1=k,2=v), n0=(y&3)*128.
__global__ __launch_bounds__(256)
void proj_all(const float* __restrict__ bq, const float* __restrict__ bk,
              const float* __restrict__ bv)
{
    __shared__ __align__(16) uint32_t sAm[3][2048];   // 8 KB per stage
    __shared__ __align__(16) uint32_t sBm[3][2048];   // 8 KB per stage

    const int tid = threadIdx.x;
    const int lane = tid & 31, wid = tid >> 5;
    const int mwarp = wid >> 2, nwarp = wid & 3;
    const int which = blockIdx.y >> 2;
    const int m0 = blockIdx.x * 128, n0 = (blockIdx.y & 3) * 128;

    const __nv_bfloat16* __restrict__ X = g_xb;
    const __nv_bfloat16* __restrict__ W = (which == 0) ? g_wq : (which == 1) ? g_wk : g_wv;
    const float* __restrict__ bias = (which == 0) ? bq : (which == 1) ? bk : bv;

    const int rowA = tid >> 1, halfA = tid & 1;
    const int rowB = tid >> 3, segB = tid & 7;
    const __nv_bfloat16* gA = X + (size_t)(m0 + rowA) * DD + halfA * 16;
    const __nv_bfloat16* gB = W + (size_t)rowB * DD + n0 + segB * 16;

    const uint32_t aBase = (uint32_t)__cvta_generic_to_shared(&sAm[0][0]);
    const uint32_t bBase = (uint32_t)__cvta_generic_to_shared(&sBm[0][0]);

    // swizzled staging addresses (bytes), same layout as the register-staged anchor
    const int usA = (rowA >> 1) & 3;
    const uint32_t aDst0 = aBase + (rowA * 16 + ((halfA * 2)     ^ usA) * 4) * 4;
    const uint32_t aDst1 = aBase + (rowA * 16 + ((halfA * 2 + 1) ^ usA) * 4) * 4;
    const int usB = rowB & 7;
    const uint32_t bDst0 = bBase + (rowB * 64 + ((segB * 2)     ^ usB) * 4) * 4;
    const uint32_t bDst1 = bBase + (rowB * 64 + ((segB * 2 + 1) ^ usB) * 4) * 4;

    auto issue = [&](int ch, int buf) {
        uint32_t o = buf * 8192;
        const __nv_bfloat16* pA = gA + ch * 32;
        const __nv_bfloat16* pB = gB + (size_t)ch * 32 * DD;
        cpa16(aDst0 + o, pA);
        cpa16(aDst1 + o, pA + 8);
        cpa16(bDst0 + o, pB);
        cpa16(bDst1 + o, pB + 8);
        asm volatile("cp.async.commit_group;\n");
    };

    float acc[4][4][4];
#pragma unroll
    for (int mi = 0; mi < 4; mi++)
#pragma unroll
        for (int ni = 0; ni < 4; ni++)
#pragma unroll
            for (int c = 0; c < 4; c++) acc[mi][ni][c] = 0.f;

    const int ro  = lane & 15;
    const int ch2 = (lane >> 4) & 1;
    const int rs2 = (ro >> 1) & 3;
    const int rs7 = ro & 7;

    issue(0, 0);
    issue(1, 1);

    for (int chn = 0; chn < 16; chn++) {
        asm volatile("cp.async.wait_group 1;\n");
        __syncthreads();
        {
            const uint32_t ab = aBase + (chn % 3) * 8192;
            const uint32_t bb = bBase + (chn % 3) * 8192;
#pragma unroll
            for (int kblk = 0; kblk < 2; kblk++) {
                uint32_t af[4][4];
#pragma unroll
                for (int mi = 0; mi < 4; mi++) {
                    int row = mwarp * 64 + mi * 16 + ro;
                    int u = (kblk * 2 + ch2) ^ rs2;
                    ldsm4(af[mi][0], af[mi][1], af[mi][2], af[mi][3],
                          ab + (row * 16 + u * 4) * 4);
                }
                uint32_t bf[2][4];
#pragma unroll
                for (int np = 0; np < 2; np++) {
                    int row = kblk * 16 + ro;
                    int u = (nwarp * 4 + np * 2 + ch2) ^ rs7;
                    ldsm4t(bf[np][0], bf[np][1], bf[np][2], bf[np][3],
                           bb + (row * 64 + u * 4) * 4);
                }
#pragma unroll
                for (int mi = 0; mi < 4; mi++)
#pragma unroll
                    for (int ni = 0; ni < 4; ni++)
                        mma16816(acc[mi][ni], af[mi],
                                 bf[ni >> 1][(ni & 1) * 2], bf[ni >> 1][(ni & 1) * 2 + 1]);
            }
        }
        if (chn + 2 < 16) issue(chn + 2, (chn + 2) % 3);
        else asm volatile("cp.async.commit_group;\n");   // keep group count aligned
    }

    const int g = lane >> 2, tig = lane & 3;

    float bn[4][2];
#pragma unroll
    for (int ni = 0; ni < 4; ni++) {
        int n = n0 + nwarp * 32 + ni * 8 + tig * 2;
        bn[ni][0] = bias[n];
        bn[ni][1] = bias[n + 1];
    }

    if (which == 0) {
        const int h = (n0 + nwarp * 32) >> 6;
#pragma unroll
        for (int mi = 0; mi < 4; mi++) {
            int m = m0 + mwarp * 64 + mi * 16 + g;
            int b = m >> 13;
            int s = m & (SS - 1);
            float ss0 = 0.f, ss1 = 0.f;
#pragma unroll
            for (int ni = 0; ni < 4; ni++) {
                float c0 = acc[mi][ni][0] + bn[ni][0];
                float c1 = acc[mi][ni][1] + bn[ni][1];
                float c2 = acc[mi][ni][2] + bn[ni][0];
                float c3 = acc[mi][ni][3] + bn[ni][1];
                ss0 = fmaf(c0, c0, fmaf(c1, c1, ss0));
                ss1 = fmaf(c2, c2, fmaf(c3, c3, ss1));
            }
            ss0 += __shfl_xor_sync(0xffffffffu, ss0, 1);
            ss0 += __shfl_xor_sync(0xffffffffu, ss0, 2);
            ss1 += __shfl_xor_sync(0xffffffffu, ss1, 1);
            ss1 += __shfl_xor_sync(0xffffffffu, ss1, 2);
            if (tig == 0) {
                atomicAdd(&g_sp[(b * HH + h) * SS + s], ss0);
                atomicAdd(&g_sp[(b * HH + h) * SS + s + 8], ss1);
            }
        }
    } else {
        __nv_bfloat16* __restrict__ dst = (which == 1) ? g_k : g_v;
#pragma unroll
        for (int mi = 0; mi < 4; mi++) {
            int m = m0 + mwarp * 64 + mi * 16 + g;
            int b = m >> 13;
            int s = m & (SS - 1);
#pragma unroll
            for (int ni = 0; ni < 4; ni++) {
                int n = n0 + nwarp * 32 + ni * 8 + tig * 2;
                int h = n >> 6, d = n & 63;
                uint32_t lo = pk(acc[mi][ni][0] + bn[ni][0], acc[mi][ni][1] + bn[ni][1]);
                uint32_t hi = pk(acc[mi][ni][2] + bn[ni][0], acc[mi][ni][3] + bn[ni][1]);
                *(uint32_t*)(dst + (((size_t)(b * HH + h)) * SS + s) * HD + d)     = lo;
                *(uint32_t*)(dst + (((size_t)(b * HH + h)) * SS + s + 8) * HD + d) = hi;
            }
        }
        if (which == 2) {
            const int b = m0 >> 13;
#pragma unroll
            for (int ni = 0; ni < 4; ni++) {
                float s0 = 0.f, s1 = 0.f;
#pragma unroll
                for (int mi = 0; mi < 4; mi++) {
                    s0 += acc[mi][ni][0] + acc[mi][ni][2];
                    s1 += acc[mi][ni][1] + acc[mi][ni][3];
                }
#pragma unroll
                for (int off = 4; off <= 16; off <<= 1) {
                    s0 += __shfl_xor_sync(0xffffffffu, s0, off);
                    s1 += __shfl_xor_sync(0xffffffffu, s1, off);
                }
                if (g == 0) {
                    int n = n0 + nwarp * 32 + ni * 8 + tig * 2;
                    atomicAdd(&g_vsum[b * DD + n], s0);
                    atomicAdd(&g_vsum[b * DD + n + 1], s1);
                }
            }
        }
    }
}

// ------------------------- histogram top-64 selection -------------------------
__global__ __launch_bounds__(256) void topk_radix()
{
    __shared__ uint32_t hist[4096];     // 16 KB
    __shared__ float    cv[2048];       // 8 KB
    __shared__ int      ci[2048];       // 8 KB
    __shared__ uint32_t gsum[256];
    __shared__ uint32_t s_thr, s_cnt;
    const int bh = blockIdx.x;
    const int tid = threadIdx.x;
#pragma unroll
    for (int i = 0; i < 16; i++) hist[tid + i * 256] = 0;
    if (tid == 0) s_cnt = 0;
    __syncthreads();

    const float* sp = g_sp + bh * SS;
    uint32_t ub[32];
#pragma unroll
    for (int i = 0; i < 32; i++) {
        ub[i] = __float_as_uint(sp[tid + i * 256]);
        atomicAdd(&hist[ub[i] >> 20], 1u);
    }
    __syncthreads();

    uint32_t gs = 0;
#pragma unroll
    for (int i = 0; i < 16; i++) gs += hist[tid * 16 + i];
    gsum[tid] = gs;
    __syncthreads();

    if (tid == 0) {
        uint32_t cum = 0;
        int g = 255;
        for (; g > 0; g--) {
            if (cum + gsum[g] >= NC) break;
            cum += gsum[g];
        }
        int b = g * 16 + 15;
        for (; b > g * 16; b--) {
            cum += hist[b];
            if (cum >= NC) break;
        }
        s_thr = (uint32_t)b;
    }
    __syncthreads();
    const uint32_t thr = s_thr;

#pragma unroll
    for (int i = 0; i < 32; i++) {
        if ((ub[i] >> 20) >= thr) {
            uint32_t p = atomicAdd(&s_cnt, 1u);
            if (p < 2048) { cv[p] = __uint_as_float(ub[i]); ci[p] = tid + i * 256; }
        }
    }
    __syncthreads();
    int C = (int)s_cnt;
    if (C > 2048) C = 2048;
    for (int c = tid; c < C; c += 256) {
        float myv = cv[c];
        int   myi = ci[c];
        int rank = 0;
        for (int j = 0; j < C; j++) {
            float o = cv[j];
            rank += (o > myv) || (o == myv && ci[j] < myi);
        }
        if (rank < NC) g_cand[bh * NC + rank] = myi;
    }
}

// ------------------------- exact fp32 recompute of candidate q rows (split-K) -----
__global__ __launch_bounds__(256)
void cand_refine(const float* __restrict__ X, const float* __restrict__ Wq,
                 const float* __restrict__ bq)
{
    __shared__ float sW[64][66];
    __shared__ float sX[8][64];
    __shared__ int   sS_[8];
    const int bh = blockIdx.x, grp = blockIdx.y, ks = blockIdx.z;
    const int b = bh >> 3, h = bh & 7;
    const int tid = threadIdx.x;
    const int u = tid >> 5, lane = tid & 31;
    if (tid < 8) sS_[tid] = g_cand[bh * NC + grp * 8 + tid];
    float acc0 = (ks == 0) ? bq[h * HD + lane * 2]     : 0.f;
    float acc1 = (ks == 0) ? bq[h * HD + lane * 2 + 1] : 0.f;
    __syncthreads();
    for (int kc = ks * 4; kc < ks * 4 + 4; kc++) {
#pragma unroll
        for (int i = 0; i < 16; i++) {
            int idx = tid + i * 256;
            sW[idx >> 6][idx & 63] = Wq[(size_t)(kc * 64 + (idx >> 6)) * DD + h * HD + (idx & 63)];
        }
#pragma unroll
        for (int i = 0; i < 2; i++) {
            int idx = tid + i * 256;
            sX[idx >> 6][idx & 63] = X[((size_t)b * SS + sS_[idx >> 6]) * DD + kc * 64 + (idx & 63)];
        }
        __syncthreads();
#pragma unroll
        for (int k = 0; k < 64; k++) {
            float xv = sX[u][k];
            float2 wv = *(const float2*)&sW[k][lane * 2];
            acc0 = fmaf(xv, wv.x, acc0);
            acc1 = fmaf(xv, wv.y, acc1);
        }
        __syncthreads();
    }
    const int cu = bh * NC + grp * 8 + u;
    atomicAdd(&g_cq[cu * HD + lane * 2], acc0);
    atomicAdd(&g_cq[cu * HD + lane * 2 + 1], acc1);
}

// ------------------------- exact top-45 among candidates (computes sumsq) ---------
__global__ __launch_bounds__(64) void final_sel()
{
    __shared__ float sq2[NC][65];   // padded: conflict-free row reads
    __shared__ float vv[NC];
    __shared__ int   ssd[NC];
    __shared__ int   slot[UU];
    const int bh = blockIdx.x;
    const int tid = threadIdx.x;
    for (int i = tid; i < NC * 64; i += 64)
        sq2[i >> 6][i & 63] = g_cq[bh * NC * HD + i];
    ssd[tid] = g_cand[bh * NC + tid];
    __syncthreads();
    float ss = 0.f;
#pragma unroll
    for (int d = 0; d < 64; d++) {
        float v = sq2[tid][d];
        ss = fmaf(v, v, ss);
    }
    vv[tid] = ss;
    __syncthreads();
    float myv = vv[tid];
    int   mys = ssd[tid];
    int rank = 0;
#pragma unroll
    for (int j = 0; j < NC; j++) {
        float o = vv[j];
        if (o > myv || (o == myv && ssd[j] < mys)) rank++;
    }
    if (rank < UU) { g_top[bh * UU + rank] = mys; slot[rank] = tid; }
    __syncthreads();
    for (int u = 0; u < UU; u++) {
        int c = slot[u];
        g_selq[(bh * UU + u) * HD + tid] = sq2[c][tid];
    }
}

// ------------------------- tensor-core flash attention (split-K over S) -----------
__global__ __launch_bounds__(256)
void attn_mma()
{
    __shared__ __align__(16) uint8_t sQ[48 * 128];    // bf16 swizzled
    __shared__ __align__(16) uint8_t sKV[64 * 128];   // K then V (bf16 swizzled)
    __shared__ __align__(16) uint8_t sPb[48 * 128];   // P bf16 swizzled
    __shared__ float sS[48][66];                      // raw scores fp32
    __shared__ float sm[48], sl[48], salpha[48];

    const int bh = blockIdx.x, sp = blockIdx.y;
    const int tid = threadIdx.x;
    const int lane = tid & 31, w = tid >> 5;
    const uint32_t qb = (uint32_t)__cvta_generic_to_shared(sQ);
    const uint32_t kb = (uint32_t)__cvta_generic_to_shared(sKV);
    const uint32_t pbm = (uint32_t)__cvta_generic_to_shared(sPb);

    for (int c = tid; c < 384; c += 256) {
        int r = c >> 3, u = c & 7;
        uint4 val = make_uint4(0, 0, 0, 0);
        if (r < UU) {
            const float* src = g_selq + ((size_t)bh * UU + r) * HD + u * 8;
            float4 f0 = *(const float4*)src;
            float4 f1 = *(const float4*)(src + 4);
            val.x = pk(f0.x * 0.125f, f0.y * 0.125f);
            val.y = pk(f0.z * 0.125f, f0.w * 0.125f);
            val.z = pk(f1.x * 0.125f, f1.y * 0.125f);
            val.w = pk(f1.z * 0.125f, f1.w * 0.125f);
        }
        *(uint4*)(sQ + r * 128 + ((u ^ (r & 7)) * 16)) = val;
    }
    if (tid < 48) { sm[tid] = -INFINITY; sl[tid] = 0.f; }

    float acc[3][4];
#pragma unroll
    for (int mt = 0; mt < 3; mt++)
#pragma unroll
        for (int c = 0; c < 4; c++) acc[mt][c] = 0.f;

    const __nv_bfloat16* kvK = g_k + ((size_t)bh * SS + sp * CHUNK) * HD;
    const __nv_bfloat16* kvV = g_v + ((size_t)bh * SS + sp * CHUNK) * HD;

    const int ro = lane & 15, ch2 = (lane >> 4) & 1;
    const int g = lane >> 2, tg = lane & 3;

    for (int t = 0; t < 8; t++) {
        __syncthreads();
        for (int c = tid; c < 512; c += 256) {
            int r = c >> 3, u = c & 7;
            uint4 val = *(const uint4*)(kvK + ((size_t)(t * 64 + r)) * HD + u * 8);
            *(uint4*)(sKV + r * 128 + ((u ^ (r & 7)) * 16)) = val;
        }
        __syncthreads();

        float Cr[3][4];
#pragma unroll
        for (int mt = 0; mt < 3; mt++)
#pragma unroll
            for (int c = 0; c < 4; c++) Cr[mt][c] = 0.f;
#pragma unroll
        for (int ks = 0; ks < 4; ks++) {
            uint32_t br[4];
            {
                int row = (w >> 1) * 16 + ro;
                ldsm4(br[0], br[1], br[2], br[3],
                      kb + row * 128 + (((ks * 2 + ch2) ^ (row & 7)) * 16));
            }
            uint32_t b0 = br[w & 1], b1 = br[(w & 1) + 2];
#pragma unroll
            for (int mt = 0; mt < 3; mt++) {
                uint32_t a[4];
                int row = mt * 16 + ro;
                ldsm4(a[0], a[1], a[2], a[3],
                      qb + row * 128 + (((ks * 2 + ch2) ^ (row & 7)) * 16));
                mma16816(Cr[mt], a, b0, b1);
            }
        }
#pragma unroll
        for (int mt = 0; mt < 3; mt++) {
            int col = w * 8 + tg * 2;
            sS[mt * 16 + g][col]     = Cr[mt][0];
            sS[mt * 16 + g][col + 1] = Cr[mt][1];
            sS[mt * 16 + g + 8][col]     = Cr[mt][2];
            sS[mt * 16 + g + 8][col + 1] = Cr[mt][3];
        }
        __syncthreads();

        for (int c = tid; c < 512; c += 256) {
            int r = c >> 3, u = c & 7;
            uint4 val = *(const uint4*)(kvV + ((size_t)(t * 64 + r)) * HD + u * 8);
            *(uint4*)(sKV + r * 128 + ((u ^ (r & 7)) * 16)) = val;
        }
        if (tid < 192) {
            int r = tid >> 2, qt = tid & 3;
            float mx = -INFINITY;
#pragma unroll
            for (int j = 0; j < 16; j++) mx = fmaxf(mx, sS[r][qt * 16 + j]);
            mx = fmaxf(mx, __shfl_xor_sync(0xffffffffu, mx, 1));
            mx = fmaxf(mx, __shfl_xor_sync(0xffffffffu, mx, 2));
            if (qt == 0) {
                float mnew = fmaxf(sm[r], mx);
                salpha[r] = __expf(sm[r] - mnew);
                sm[r] = mnew;
            }
        }
        __syncthreads();

#pragma unroll
        for (int mt = 0; mt < 3; mt++) {
            float a0 = salpha[mt * 16 + g];
            float a1 = salpha[mt * 16 + g + 8];
            acc[mt][0] *= a0; acc[mt][1] *= a0;
            acc[mt][2] *= a1; acc[mt][3] *= a1;
        }
        if (tid < 192) {
            int r = tid >> 2, qt = tid & 3;
            float mr = sm[r];
            float e[16], ls = 0.f;
#pragma unroll
            for (int j = 0; j < 16; j++) {
                e[j] = __expf(sS[r][qt * 16 + j] - mr);
                ls += e[j];
            }
            uint4 v0, v1;
            v0.x = pk(e[0], e[1]);   v0.y = pk(e[2], e[3]);
            v0.z = pk(e[4], e[5]);   v0.w = pk(e[6], e[7]);
            v1.x = pk(e[8], e[9]);   v1.y = pk(e[10], e[11]);
            v1.z = pk(e[12], e[13]); v1.w = pk(e[14], e[15]);
            *(uint4*)(sPb + r * 128 + (((qt * 2)     ^ (r & 7)) * 16)) = v0;
            *(uint4*)(sPb + r * 128 + (((qt * 2 + 1) ^ (r & 7)) * 16)) = v1;
            ls += __shfl_xor_sync(0xffffffffu, ls, 1);
            ls += __shfl_xor_sync(0xffffffffu, ls, 2);
            if (qt == 0) sl[r] = sl[r] * salpha[r] + ls;
        }
        __syncthreads();

#pragma unroll
        for (int ks = 0; ks < 4; ks++) {
            uint32_t br[4];
            {
                int row = ks * 16 + ro;
                ldsm4t(br[0], br[1], br[2], br[3],
                       kb + row * 128 + ((((w >> 1) * 2 + ch2) ^ (row & 7)) * 16));
            }
            uint32_t b0 = br[(w & 1) * 2], b1 = br[(w & 1) * 2 + 1];
#pragma unroll
            for (int mt = 0; mt < 3; mt++) {
                uint32_t a[4];
                int row = mt * 16 + ro;
                ldsm4(a[0], a[1], a[2], a[3],
                      pbm + row * 128 + (((ks * 2 + ch2) ^ (row & 7)) * 16));
                mma16816(acc[mt], a, b0, b1);
            }
        }
    }

    const int pbase = (bh * NSPLIT + sp) * UU;
    if (tid < UU) { g_pm[pbase + tid] = sm[tid]; g_pl[pbase + tid] = sl[tid]; }
#pragma unroll
    for (int mt = 0; mt < 3; mt++) {
        int q0 = mt * 16 + g, q1 = q0 + 8;
        int d = w * 8 + tg * 2;
        if (q0 < UU)
            *(float2*)(g_pacc + ((size_t)(pbase + q0)) * HD + d) = make_float2(acc[mt][0], acc[mt][1]);
        if (q1 < UU)
            *(float2*)(g_pacc + ((size_t)(pbase + q1)) * HD + d) = make_float2(acc[mt][2], acc[mt][3]);
    }
}

// ------------------------- split-K merge -------------------------
__global__ __launch_bounds__(64) void merge_kernel()
{
    const int bh = blockIdx.x, u = blockIdx.y;
    const int d = threadIdx.x;
    float M = -INFINITY;
#pragma unroll
    for (int i = 0; i < NSPLIT; i++)
        M = fmaxf(M, g_pm[(bh * NSPLIT + i) * UU + u]);
    float L = 0.f, ctx = 0.f;
    for (int i = 0; i < NSPLIT; i++) {
        int pi = (bh * NSPLIT + i) * UU + u;
        float w = __expf(g_pm[pi] - M);
        L += g_pl[pi] * w;
        ctx += g_pacc[(size_t)pi * HD + d] * w;
    }
    g_selctx[(bh * UU + u) * HD + d] = ctx / L;
}

// ------------------------- output base, broadcast, corrections -------------------------
__global__ __launch_bounds__(512)
void base_kernel(const float* __restrict__ Wo, const float* __restrict__ bo,
                 const float* __restrict__ bv)
{
    __shared__ float vm[DD];
    const int b = blockIdx.x;
    const int n = threadIdx.x;
    vm[n] = g_vsum[b * DD + n] * (1.f / SS) + bv[n];
    __syncthreads();
    float a = bo[n];
    for (int kk = 0; kk < DD; kk++)
        a = fmaf(vm[kk], Wo[(size_t)kk * DD + n], a);
    g_base[b * DD + n] = a;
}

__global__ __launch_bounds__(256) void bcast_kernel(float* __restrict__ out)
{
    __shared__ float4 bs[128];
    const int row0 = blockIdx.x * 16;
    const int b = row0 >> 13;
    if (threadIdx.x < 128)
        bs[threadIdx.x] = ((const float4*)(g_base + b * DD))[threadIdx.x];
    __syncthreads();
    float4* o = (float4*)out + (size_t)row0 * 128;
    for (int i = threadIdx.x; i < 16 * 128; i += 256)
        o[i] = bs[i & 127];
}

__global__ __launch_bounds__(512)
void corr_kernel(const float* __restrict__ Wo, const float* __restrict__ bv,
                 float* __restrict__ out)
{
    __shared__ float delta[64];
    __shared__ int ssel;
    const int bh = blockIdx.x, u = blockIdx.y;
    const int b = bh >> 3, h = bh & 7;
    const int tid = threadIdx.x;
    if (tid == 0) ssel = g_top[bh * UU + u];
    if (tid < 64)
        delta[tid] = g_selctx[(bh * UU + u) * HD + tid]
                   - (g_vsum[bh * HD + tid] * (1.f / SS) + bv[h * HD + tid]);
    __syncthreads();
    const int s = ssel;
    float a = 0.f;
#pragma unroll
    for (int d = 0; d < 64; d++)
        a = fmaf(delta[d], Wo[(size_t)(h * HD + d) * DD + tid], a);
    atomicAdd(out + ((size_t)b * SS + s) * DD + tid, a);
}

// ------------------------- launch -------------------------
extern "C" void kernel_launch(void* const* d_in, const int* in_sizes, int n_in,
                              void* d_out, int out_size)
{
    (void)in_sizes; (void)n_in; (void)out_size;
    const float* x  = (const float*)d_in[0];
    const float* Wq = (const float*)d_in[1];
    const float* bq = (const float*)d_in[2];
    const float* Wk = (const float*)d_in[3];
    const float* bk = (const float*)d_in[4];
    const float* Wv = (const float*)d_in[5];
    const float* bv = (const float*)d_in[6];
    const float* Wo = (const float*)d_in[7];
    const float* bo = (const float*)d_in[8];
    float* out = (float*)d_out;

    cvt_all<<<18176, 256>>>(x, Wq, Wk, Wv);
    proj_all<<<dim3(256, 12), 256>>>(bq, bk, bv);
    topk_radix<<<BH, 256>>>();
    cand_refine<<<dim3(BH, NC / 8, 2), 256>>>(x, Wq, bq);
    final_sel<<<BH, 64>>>();
    attn_mma<<<dim3(BH, NSPLIT), 256>>>();
    merge_kernel<<<dim3(BH, UU), HD>>>();
    base_kernel<<<BB, DD>>>(Wo, bo, bv);
    bcast_kernel<<<BB * SS / 16, 256>>>(out);
    corr_kernel<<<dim3(BH, UU), DD>>>(Wo, bv, out);
}